// round 2
// baseline (speedup 1.0000x reference)
#include <cuda_runtime.h>

#define BATCH 8192
#define T 50
#define F 17
#define HID 64
#define GATES 256     // 4*HID
#define INPD 34       // 2*F
#define BT 64         // batch rows per block
#define NB (BATCH/BT) // 128 blocks
#define NTHREADS 256

typedef unsigned long long ull;

// Deterministic per-(t, block) loss partials (no atomics in the sum).
__device__ float g_num[T * NB];
__device__ float g_den[T * NB];
__device__ unsigned int g_cnt;   // zero-init; reset to 0 by finalizing block

struct Smem {
    float Wtd[F][HID];          // [k][out]
    float WregT[F][HID + 2];    // [f][k], padded to kill bank conflicts
    float Wih[INPD][GATES];     // [k][out]
    float Whh[HID][GATES];      // [k][out]
    float H[BT][HID];           // scalar h
    float C[BT][HID];
    float2 H2[BT][HID];         // duplicated {h,h} for f32x2 broadcast
    float2 Inp2[BT][INPD];      // duplicated {v,v}: [x_c | m]
    float X[BT][F];
    float M[BT][F];
    float D[BT][F];
    float btd[HID];
    float bih[GATES];           // b_ih + b_hh
    float Wout[HID];
    float red[16];
    float breg[F];
    float bout;
    int   flagi;
    float sv[64];
};

__device__ __forceinline__ ull pk2(float a, float b) {
    ull r;
    asm("mov.b64 %0, {%1, %2};" : "=l"(r) : "f"(a), "f"(b));
    return r;
}
__device__ __forceinline__ float2 up2(ull v) {
    float2 f;
    asm("mov.b64 {%0, %1}, %2;" : "=f"(f.x), "=f"(f.y) : "l"(v));
    return f;
}
__device__ __forceinline__ ull fma2(ull a, ull b, ull c) {
    ull d;
    asm("fma.rn.f32x2 %0, %1, %2, %3;" : "=l"(d) : "l"(a), "l"(b), "l"(c));
    return d;
}

__device__ __forceinline__ float sigm(float x) {
    return __fdividef(1.0f, 1.0f + __expf(-x));
}
__device__ __forceinline__ float tanh_acc(float x) {
    return __fdividef(2.0f, 1.0f + __expf(-2.0f * x)) - 1.0f;
}

__global__ void __launch_bounds__(NTHREADS, 1)
grud_kernel(const float* __restrict__ values,
            const float* __restrict__ masks,
            const float* __restrict__ deltas,
            const float* __restrict__ Wtd, const float* __restrict__ btd,
            const float* __restrict__ Wreg, const float* __restrict__ breg,
            const float* __restrict__ Wih, const float* __restrict__ Whh,
            const float* __restrict__ bih, const float* __restrict__ bhh,
            const float* __restrict__ Wout, const float* __restrict__ bout,
            float* __restrict__ out_loss,  // [1]
            float* __restrict__ out_imp,   // [B, T, F]
            float* __restrict__ out_yh)    // [B]
{
    extern __shared__ float smem_raw[];
    Smem& s = *reinterpret_cast<Smem*>(smem_raw);
    const int tid = threadIdx.x;
    const int bb = blockIdx.x * BT;

    // ---- load + transpose weights into shared ----
    for (int i = tid; i < F * HID; i += NTHREADS) {
        int k = i / HID, j = i % HID;
        s.Wtd[k][j] = Wtd[j * F + k];
    }
    for (int i = tid; i < F * HID; i += NTHREADS) {
        int f = i / HID, k = i % HID;
        s.WregT[f][k] = Wreg[f * HID + k];   // already [f][k] row-major
    }
    for (int i = tid; i < INPD * GATES; i += NTHREADS) {
        int k = i / GATES, j = i % GATES;
        s.Wih[k][j] = Wih[j * INPD + k];
    }
    for (int i = tid; i < HID * GATES; i += NTHREADS) {
        int k = i / GATES, j = i % GATES;
        s.Whh[k][j] = Whh[j * HID + k];
    }
    if (tid < HID) s.btd[tid] = btd[tid];
    if (tid < F)   s.breg[tid] = breg[tid];
    if (tid < GATES) s.bih[tid] = bih[tid] + bhh[tid];
    if (tid < HID) s.Wout[tid] = Wout[tid];
    if (tid == 0)  s.bout = bout[0];
    for (int i = tid; i < BT * HID; i += NTHREADS) {
        s.H[i / HID][i % HID] = 0.0f;
        s.C[i / HID][i % HID] = 0.0f;
    }
    __syncthreads();

    const int w = tid >> 5;        // warp id 0..7 -> owns rows r0..r0+7
    const int l = tid & 31;        // lane -> owns hidden units h0, h0+1
    const int r0 = w * 8;
    const int h0 = l * 2;

    for (int t = 0; t < T; t++) {
        // ---- phase 1: load x, m, d ----
        for (int o = tid; o < BT * F; o += NTHREADS) {
            int r = o / F, f = o % F;
            int base = (bb + r) * (T * F) + t * F + f;
            float xv = values[base];
            xv = (xv != xv) ? 0.0f : xv;   // nan -> 0
            float mv = masks[base];
            s.X[r][f] = xv;
            s.M[r][f] = mv;
            s.D[r][f] = deltas[base];
            s.Inp2[r][F + f] = make_float2(mv, mv);
        }
        __syncthreads();

        // ---- phase 2: gamma = exp(-relu(d@Wtd^T + btd)); h *= gamma; dup into H2 ----
        {
            ull a2[8];
            ull b2 = *(const ull*)&s.btd[h0];
            #pragma unroll
            for (int i = 0; i < 8; i++) a2[i] = b2;
            #pragma unroll
            for (int k = 0; k < F; k++) {
                ull wv = *(const ull*)&s.Wtd[k][h0];
                #pragma unroll
                for (int i = 0; i < 8; i++) {
                    float dv = s.D[r0 + i][k];
                    a2[i] = fma2(wv, pk2(dv, dv), a2[i]);
                }
            }
            #pragma unroll
            for (int i = 0; i < 8; i++) {
                float2 a = up2(a2[i]);
                float g0 = __expf(-fmaxf(a.x, 0.0f));
                float g1 = __expf(-fmaxf(a.y, 0.0f));
                float2* hp = (float2*)&s.H[r0 + i][h0];
                float2 hv = *hp;
                hv.x *= g0; hv.y *= g1;
                *hp = hv;
                s.H2[r0 + i][h0]     = make_float2(hv.x, hv.x);
                s.H2[r0 + i][h0 + 1] = make_float2(hv.y, hv.y);
            }
        }
        __syncthreads();

        // ---- phase 3: x_h = h@Wreg^T + breg; x_c; loss; imputation ----
        float lnum = 0.0f, lden = 0.0f;
        for (int o = tid; o < BT * F; o += NTHREADS) {
            int r = o / F, f = o % F;
            ull acc2 = 0ULL;  // {0,0}
            #pragma unroll 8
            for (int k = 0; k < HID; k += 2) {
                ull h2 = *(const ull*)&s.H[r][k];
                ull w2 = *(const ull*)&s.WregT[f][k];
                acc2 = fma2(h2, w2, acc2);
            }
            float2 ap = up2(acc2);
            float acc = ap.x + ap.y + s.breg[f];
            float xv = s.X[r][f];
            float mv = s.M[r][f];
            float xc = mv * xv + (1.0f - mv) * acc;
            s.Inp2[r][f] = make_float2(xc, xc);
            lnum += fabsf(xv - acc) * mv;
            lden += mv;
            out_imp[(bb + r) * (T * F) + t * F + f] = xc;
        }
        #pragma unroll
        for (int ofs = 16; ofs > 0; ofs >>= 1) {
            lnum += __shfl_down_sync(0xFFFFFFFFu, lnum, ofs);
            lden += __shfl_down_sync(0xFFFFFFFFu, lden, ofs);
        }
        if (l == 0) { s.red[w] = lnum; s.red[8 + w] = lden; }
        __syncthreads();
        if (tid == 0) {
            float n = 0.0f, d = 0.0f;
            #pragma unroll
            for (int i = 0; i < 8; i++) { n += s.red[i]; d += s.red[8 + i]; }
            g_num[t * NB + blockIdx.x] = n;
            g_den[t * NB + blockIdx.x] = d;
        }

        // ---- phase 4: gates GEMM (f32x2) + LSTM update ----
        {
            ull ai[8], af[8], ag[8], ao[8];
            ull bi = *(const ull*)&s.bih[h0];
            ull bf = *(const ull*)&s.bih[64 + h0];
            ull bg = *(const ull*)&s.bih[128 + h0];
            ull bo = *(const ull*)&s.bih[192 + h0];
            #pragma unroll
            for (int i = 0; i < 8; i++) { ai[i] = bi; af[i] = bf; ag[i] = bg; ao[i] = bo; }

            #pragma unroll 2
            for (int k = 0; k < INPD; k++) {
                ull wi = *(const ull*)&s.Wih[k][h0];
                ull wf = *(const ull*)&s.Wih[k][64 + h0];
                ull wg = *(const ull*)&s.Wih[k][128 + h0];
                ull wo = *(const ull*)&s.Wih[k][192 + h0];
                #pragma unroll
                for (int i = 0; i < 8; i++) {
                    ull v2 = *(const ull*)&s.Inp2[r0 + i][k];
                    ai[i] = fma2(wi, v2, ai[i]);
                    af[i] = fma2(wf, v2, af[i]);
                    ag[i] = fma2(wg, v2, ag[i]);
                    ao[i] = fma2(wo, v2, ao[i]);
                }
            }
            #pragma unroll 2
            for (int k = 0; k < HID; k++) {
                ull wi = *(const ull*)&s.Whh[k][h0];
                ull wf = *(const ull*)&s.Whh[k][64 + h0];
                ull wg = *(const ull*)&s.Whh[k][128 + h0];
                ull wo = *(const ull*)&s.Whh[k][192 + h0];
                #pragma unroll
                for (int i = 0; i < 8; i++) {
                    ull v2 = *(const ull*)&s.H2[r0 + i][k];
                    ai[i] = fma2(wi, v2, ai[i]);
                    af[i] = fma2(wf, v2, af[i]);
                    ag[i] = fma2(wg, v2, ag[i]);
                    ao[i] = fma2(wo, v2, ao[i]);
                }
            }
            #pragma unroll
            for (int i = 0; i < 8; i++) {
                float2 vi = up2(ai[i]);
                float2 vf = up2(af[i]);
                float2 vg = up2(ag[i]);
                float2 vo = up2(ao[i]);
                float2* cp = (float2*)&s.C[r0 + i][h0];
                float2 cv = *cp;
                float iv0 = sigm(vi.x), iv1 = sigm(vi.y);
                float fv0 = sigm(vf.x), fv1 = sigm(vf.y);
                float gv0 = tanh_acc(vg.x), gv1 = tanh_acc(vg.y);
                float ov0 = sigm(vo.x), ov1 = sigm(vo.y);
                float c0 = fv0 * cv.x + iv0 * gv0;
                float c1 = fv1 * cv.y + iv1 * gv1;
                cv.x = c0; cv.y = c1;
                *cp = cv;
                float2* hp = (float2*)&s.H[r0 + i][h0];
                float2 hv;
                hv.x = ov0 * tanh_acc(c0);
                hv.y = ov1 * tanh_acc(c1);
                *hp = hv;
            }
        }
        __syncthreads();
    }

    // ---- y_h = h_final @ Wout^T + bout ----
    if (tid < BT) {
        float acc = s.bout;
        #pragma unroll 8
        for (int k = 0; k < HID; k++) acc += s.H[tid][k] * s.Wout[k];
        out_yh[bb + tid] = acc;
    }

    // ---- folded finalize: last block to arrive sums the loss partials ----
    if (tid == 0) {
        __threadfence();
        unsigned int prev = atomicAdd(&g_cnt, 1u);
        s.flagi = (prev == NB - 1) ? 1 : 0;
    }
    __syncthreads();
    if (s.flagi) {
        __threadfence();
        float v = 0.0f;
        if (tid < T) {
            float n = 0.0f, d = 0.0f;
            for (int b = 0; b < NB; b++) {
                n += g_num[tid * NB + b];
                d += g_den[tid * NB + b];
            }
            v = n / (d + 1e-5f);
        }
        if (tid < 64) s.sv[tid] = v;
        __syncthreads();
        if (tid < 32) {
            float x = s.sv[tid] + s.sv[tid + 32];
            #pragma unroll
            for (int ofs = 16; ofs > 0; ofs >>= 1)
                x += __shfl_down_sync(0xFFFFFFFFu, x, ofs);
            if (tid == 0) {
                out_loss[0] = x;
                g_cnt = 0;  // reset for next launch
            }
        }
    }
}

extern "C" void kernel_launch(void* const* d_in, const int* in_sizes, int n_in,
                              void* d_out, int out_size) {
    const float* values = (const float*)d_in[0];
    const float* masks  = (const float*)d_in[1];
    const float* deltas = (const float*)d_in[2];
    const float* Wtd    = (const float*)d_in[3];
    const float* btd    = (const float*)d_in[4];
    const float* Wreg   = (const float*)d_in[5];
    const float* breg   = (const float*)d_in[6];
    const float* Wih    = (const float*)d_in[7];
    const float* Whh    = (const float*)d_in[8];
    const float* bih    = (const float*)d_in[9];
    const float* bhh    = (const float*)d_in[10];
    const float* Wout   = (const float*)d_in[11];
    const float* bout   = (const float*)d_in[12];

    float* out = (float*)d_out;
    float* out_loss = out;                       // [1]
    float* out_imp  = out + 1;                   // [B, T, F]
    float* out_yh   = out + 1 + BATCH * T * F;   // [B, 1]

    cudaFuncSetAttribute(grud_kernel,
                         cudaFuncAttributeMaxDynamicSharedMemorySize,
                         (int)sizeof(Smem));
    grud_kernel<<<NB, NTHREADS, sizeof(Smem)>>>(
        values, masks, deltas, Wtd, btd, Wreg, breg,
        Wih, Whh, bih, bhh, Wout, bout, out_loss, out_imp, out_yh);
}

// round 3
// speedup vs baseline: 1.1311x; 1.1311x over previous
#include <cuda_runtime.h>

#define BATCH 8192
#define T 50
#define F 17
#define HID 64
#define GATES 256     // 4*HID
#define INPD 34       // 2*F
#define BT 64         // batch rows per block
#define NB (BATCH/BT) // 128 blocks
#define NTHREADS 512
#define NW (NTHREADS/32)

// Deterministic per-(t, block) loss partials.
__device__ float g_num[T * NB];
__device__ float g_den[T * NB];
__device__ unsigned int g_cnt;   // zero-init; reset by finalizing block

struct Smem {
    float Wtd[F][HID];          // [k][out]
    float WregT[F][HID + 2];    // [f][k], padded
    float Wih[INPD][GATES];     // [k][out]
    float Whh[HID][GATES];      // [k][out]
    float H[BT][HID];
    float C[BT][HID];
    float Inp[BT][INPD];        // [x_c | m]
    float X[2][BT][F];
    float M[2][BT][F];
    float D[2][BT][F];
    float btd[HID];
    float bih[GATES];           // b_ih + b_hh
    float Wout[HID];
    float red[2 * NW];
    float breg[F];
    float bout;
    int   flagi;
    float sv[64];
};

__device__ __forceinline__ float sigm(float x) {
    return __fdividef(1.0f, 1.0f + __expf(-x));
}
__device__ __forceinline__ float tanh_acc(float x) {
    return __fdividef(2.0f, 1.0f + __expf(-2.0f * x)) - 1.0f;
}

__global__ void __launch_bounds__(NTHREADS, 1)
grud_kernel(const float* __restrict__ values,
            const float* __restrict__ masks,
            const float* __restrict__ deltas,
            const float* __restrict__ Wtd, const float* __restrict__ btd,
            const float* __restrict__ Wreg, const float* __restrict__ breg,
            const float* __restrict__ Wih, const float* __restrict__ Whh,
            const float* __restrict__ bih, const float* __restrict__ bhh,
            const float* __restrict__ Wout, const float* __restrict__ bout,
            float* __restrict__ out_loss,  // [1]
            float* __restrict__ out_imp,   // [B, T, F]
            float* __restrict__ out_yh)    // [B]
{
    extern __shared__ float smem_raw[];
    Smem& s = *reinterpret_cast<Smem*>(smem_raw);
    const int tid = threadIdx.x;
    const int bb = blockIdx.x * BT;

    // ---- load + transpose weights; load t=0 inputs ----
    for (int i = tid; i < F * HID; i += NTHREADS) {
        int k = i / HID, j = i % HID;
        s.Wtd[k][j] = Wtd[j * F + k];
    }
    for (int i = tid; i < F * HID; i += NTHREADS) {
        int f = i / HID, k = i % HID;
        s.WregT[f][k] = Wreg[f * HID + k];
    }
    for (int i = tid; i < INPD * GATES; i += NTHREADS) {
        int k = i / GATES, j = i % GATES;
        s.Wih[k][j] = Wih[j * INPD + k];
    }
    for (int i = tid; i < HID * GATES; i += NTHREADS) {
        int k = i / GATES, j = i % GATES;
        s.Whh[k][j] = Whh[j * HID + k];
    }
    if (tid < HID) s.btd[tid] = btd[tid];
    if (tid < F)   s.breg[tid] = breg[tid];
    if (tid < GATES) s.bih[tid] = bih[tid] + bhh[tid];
    if (tid < HID) s.Wout[tid] = Wout[tid];
    if (tid == 0)  s.bout = bout[0];
    for (int i = tid; i < BT * HID; i += NTHREADS) {
        s.H[i / HID][i % HID] = 0.0f;
        s.C[i / HID][i % HID] = 0.0f;
    }
    // t=0 inputs into buffer 0
    for (int o = tid; o < BT * F; o += NTHREADS) {
        int r = o / F, f = o % F;
        int base = (bb + r) * (T * F) + f;   // t=0
        float xv = values[base];
        xv = (xv != xv) ? 0.0f : xv;
        s.X[0][r][f] = xv;
        s.M[0][r][f] = masks[base];
        s.D[0][r][f] = deltas[base];
    }
    __syncthreads();

    const int w = tid >> 5;        // warp id 0..15 -> rows r0..r0+3
    const int l = tid & 31;        // lane -> hidden units h0, h0+1
    const int r0 = w * 4;
    const int h0 = l * 2;

    for (int t = 0; t < T; t++) {
        const int cur = t & 1;
        const int nxt = cur ^ 1;

        // ---- prefetch t+1 inputs into registers (overlaps with compute) ----
        float pX[3], pM[3], pD[3];
        const bool pf3 = (tid < BT * F - 2 * NTHREADS);  // 1088 - 1024 = 64
        if (t + 1 < T) {
            #pragma unroll
            for (int j = 0; j < 2; j++) {
                int o = tid + j * NTHREADS;
                int r = o / F, f = o % F;
                int base = (bb + r) * (T * F) + (t + 1) * F + f;
                pX[j] = values[base];
                pM[j] = masks[base];
                pD[j] = deltas[base];
            }
            if (pf3) {
                int o = tid + 2 * NTHREADS;
                int r = o / F, f = o % F;
                int base = (bb + r) * (T * F) + (t + 1) * F + f;
                pX[2] = values[base];
                pM[2] = masks[base];
                pD[2] = deltas[base];
            }
        }

        // ---- phase 2: gamma = exp(-relu(d@Wtd^T + btd)); h *= gamma ----
        {
            float a0[4], a1[4];
            #pragma unroll
            for (int i = 0; i < 4; i++) { a0[i] = s.btd[h0]; a1[i] = s.btd[h0 + 1]; }
            #pragma unroll
            for (int k = 0; k < F; k++) {
                float2 wv = *(const float2*)&s.Wtd[k][h0];
                #pragma unroll
                for (int i = 0; i < 4; i++) {
                    float dv = s.D[cur][r0 + i][k];
                    a0[i] += dv * wv.x;
                    a1[i] += dv * wv.y;
                }
            }
            #pragma unroll
            for (int i = 0; i < 4; i++) {
                float g0 = __expf(-fmaxf(a0[i], 0.0f));
                float g1 = __expf(-fmaxf(a1[i], 0.0f));
                float2* hp = (float2*)&s.H[r0 + i][h0];
                float2 hv = *hp;
                hv.x *= g0; hv.y *= g1;
                *hp = hv;
            }
        }
        __syncthreads();

        // ---- phase 3: x_h, x_c, loss partials, imputation ----
        float lnum = 0.0f, lden = 0.0f;
        for (int o = tid; o < BT * F; o += NTHREADS) {
            int r = o / F, f = o % F;
            float acc = s.breg[f];
            #pragma unroll 8
            for (int k = 0; k < HID; k += 2) {
                float2 h2 = *(const float2*)&s.H[r][k];
                float2 w2 = *(const float2*)&s.WregT[f][k];
                acc += h2.x * w2.x;
                acc += h2.y * w2.y;
            }
            float xv = s.X[cur][r][f];
            float mv = s.M[cur][r][f];
            float xc = mv * xv + (1.0f - mv) * acc;
            s.Inp[r][f] = xc;
            s.Inp[r][F + f] = mv;
            lnum += fabsf(xv - acc) * mv;
            lden += mv;
            out_imp[(bb + r) * (T * F) + t * F + f] = xc;
        }
        #pragma unroll
        for (int ofs = 16; ofs > 0; ofs >>= 1) {
            lnum += __shfl_down_sync(0xFFFFFFFFu, lnum, ofs);
            lden += __shfl_down_sync(0xFFFFFFFFu, lden, ofs);
        }
        if (l == 0) { s.red[w] = lnum; s.red[NW + w] = lden; }
        __syncthreads();
        if (tid == 0) {
            float n = 0.0f, d = 0.0f;
            #pragma unroll
            for (int i = 0; i < NW; i++) { n += s.red[i]; d += s.red[NW + i]; }
            g_num[t * NB + blockIdx.x] = n;
            g_den[t * NB + blockIdx.x] = d;
        }

        // ---- phase 4: gates GEMM + LSTM update ----
        {
            float ai0[4], ai1[4], af0[4], af1[4], ag0[4], ag1[4], ao0[4], ao1[4];
            #pragma unroll
            for (int i = 0; i < 4; i++) {
                ai0[i] = s.bih[h0];           ai1[i] = s.bih[h0 + 1];
                af0[i] = s.bih[64 + h0];      af1[i] = s.bih[64 + h0 + 1];
                ag0[i] = s.bih[128 + h0];     ag1[i] = s.bih[128 + h0 + 1];
                ao0[i] = s.bih[192 + h0];     ao1[i] = s.bih[192 + h0 + 1];
            }
            #pragma unroll 2
            for (int k = 0; k < INPD; k++) {
                float2 wi = *(const float2*)&s.Wih[k][h0];
                float2 wf = *(const float2*)&s.Wih[k][64 + h0];
                float2 wg = *(const float2*)&s.Wih[k][128 + h0];
                float2 wo = *(const float2*)&s.Wih[k][192 + h0];
                #pragma unroll
                for (int i = 0; i < 4; i++) {
                    float v = s.Inp[r0 + i][k];
                    ai0[i] += v * wi.x; ai1[i] += v * wi.y;
                    af0[i] += v * wf.x; af1[i] += v * wf.y;
                    ag0[i] += v * wg.x; ag1[i] += v * wg.y;
                    ao0[i] += v * wo.x; ao1[i] += v * wo.y;
                }
            }
            #pragma unroll 2
            for (int k = 0; k < HID; k++) {
                float2 wi = *(const float2*)&s.Whh[k][h0];
                float2 wf = *(const float2*)&s.Whh[k][64 + h0];
                float2 wg = *(const float2*)&s.Whh[k][128 + h0];
                float2 wo = *(const float2*)&s.Whh[k][192 + h0];
                #pragma unroll
                for (int i = 0; i < 4; i++) {
                    float v = s.H[r0 + i][k];
                    ai0[i] += v * wi.x; ai1[i] += v * wi.y;
                    af0[i] += v * wf.x; af1[i] += v * wf.y;
                    ag0[i] += v * wg.x; ag1[i] += v * wg.y;
                    ao0[i] += v * wo.x; ao1[i] += v * wo.y;
                }
            }
            #pragma unroll
            for (int i = 0; i < 4; i++) {
                float2* cp = (float2*)&s.C[r0 + i][h0];
                float2 cv = *cp;
                float iv0 = sigm(ai0[i]), iv1 = sigm(ai1[i]);
                float fv0 = sigm(af0[i]), fv1 = sigm(af1[i]);
                float gv0 = tanh_acc(ag0[i]), gv1 = tanh_acc(ag1[i]);
                float ov0 = sigm(ao0[i]), ov1 = sigm(ao1[i]);
                float c0 = fv0 * cv.x + iv0 * gv0;
                float c1 = fv1 * cv.y + iv1 * gv1;
                cv.x = c0; cv.y = c1;
                *cp = cv;
                float2* hp = (float2*)&s.H[r0 + i][h0];
                float2 hv;
                hv.x = ov0 * tanh_acc(c0);
                hv.y = ov1 * tanh_acc(c1);
                *hp = hv;
            }
        }

        // ---- store prefetched t+1 inputs ----
        if (t + 1 < T) {
            #pragma unroll
            for (int j = 0; j < 2; j++) {
                int o = tid + j * NTHREADS;
                int r = o / F, f = o % F;
                float xv = pX[j];
                xv = (xv != xv) ? 0.0f : xv;
                s.X[nxt][r][f] = xv;
                s.M[nxt][r][f] = pM[j];
                s.D[nxt][r][f] = pD[j];
            }
            if (pf3) {
                int o = tid + 2 * NTHREADS;
                int r = o / F, f = o % F;
                float xv = pX[2];
                xv = (xv != xv) ? 0.0f : xv;
                s.X[nxt][r][f] = xv;
                s.M[nxt][r][f] = pM[2];
                s.D[nxt][r][f] = pD[2];
            }
        }
        __syncthreads();
    }

    // ---- y_h = h_final @ Wout^T + bout ----
    if (tid < BT) {
        float acc = s.bout;
        #pragma unroll 8
        for (int k = 0; k < HID; k++) acc += s.H[tid][k] * s.Wout[k];
        out_yh[bb + tid] = acc;
    }

    // ---- folded finalize ----
    if (tid == 0) {
        __threadfence();
        unsigned int prev = atomicAdd(&g_cnt, 1u);
        s.flagi = (prev == NB - 1) ? 1 : 0;
    }
    __syncthreads();
    if (s.flagi) {
        __threadfence();
        float v = 0.0f;
        if (tid < T) {
            float n = 0.0f, d = 0.0f;
            for (int b = 0; b < NB; b++) {
                n += g_num[tid * NB + b];
                d += g_den[tid * NB + b];
            }
            v = n / (d + 1e-5f);
        }
        if (tid < 64) s.sv[tid] = v;
        __syncthreads();
        if (tid < 32) {
            float x = s.sv[tid] + s.sv[tid + 32];
            #pragma unroll
            for (int ofs = 16; ofs > 0; ofs >>= 1)
                x += __shfl_down_sync(0xFFFFFFFFu, x, ofs);
            if (tid == 0) {
                out_loss[0] = x;
                g_cnt = 0;
            }
        }
    }
}

extern "C" void kernel_launch(void* const* d_in, const int* in_sizes, int n_in,
                              void* d_out, int out_size) {
    const float* values = (const float*)d_in[0];
    const float* masks  = (const float*)d_in[1];
    const float* deltas = (const float*)d_in[2];
    const float* Wtd    = (const float*)d_in[3];
    const float* btd    = (const float*)d_in[4];
    const float* Wreg   = (const float*)d_in[5];
    const float* breg   = (const float*)d_in[6];
    const float* Wih    = (const float*)d_in[7];
    const float* Whh    = (const float*)d_in[8];
    const float* bih    = (const float*)d_in[9];
    const float* bhh    = (const float*)d_in[10];
    const float* Wout   = (const float*)d_in[11];
    const float* bout   = (const float*)d_in[12];

    float* out = (float*)d_out;
    float* out_loss = out;                       // [1]
    float* out_imp  = out + 1;                   // [B, T, F]
    float* out_yh   = out + 1 + BATCH * T * F;   // [B, 1]

    cudaFuncSetAttribute(grud_kernel,
                         cudaFuncAttributeMaxDynamicSharedMemorySize,
                         (int)sizeof(Smem));
    grud_kernel<<<NB, NTHREADS, sizeof(Smem)>>>(
        values, masks, deltas, Wtd, btd, Wreg, breg,
        Wih, Whh, bih, bhh, Wout, bout, out_loss, out_imp, out_yh);
}

// round 4
// speedup vs baseline: 1.1325x; 1.0012x over previous
#include <cuda_runtime.h>

#define BATCH 8192
#define T 50
#define F 17
#define HID 64
#define GATES 256     // 4*HID
#define INPD 34       // 2*F
#define BT 64         // batch rows per block
#define NB (BATCH/BT) // 128 blocks
#define NTHREADS 512
#define NW (NTHREADS/32)

// Deterministic per-(t, block) loss partials.
__device__ float g_num[T * NB];
__device__ float g_den[T * NB];
__device__ unsigned int g_cnt;   // zero-init; reset by finalizing block

struct Smem {
    float Wtd[F][HID];          // [k][out]
    float WregT[F][HID + 2];    // [f][k], padded
    float Wih[INPD][GATES];     // [k][out]
    float Whh[HID][GATES];      // [k][out]
    float H[BT][HID];
    float C[BT][HID];
    float Inp[BT][INPD];        // [x_c | m]
    float X[2][BT][F];
    float M[2][BT][F];
    float D[2][BT][F];
    float btd[HID];
    float bih[GATES];           // b_ih + b_hh
    float Wout[HID];
    float red[2 * NW];
    float breg[F];
    float bout;
    int   flagi;
    float sv[64];
};

__device__ __forceinline__ float sigm(float x) {
    return __fdividef(1.0f, 1.0f + __expf(-x));
}
__device__ __forceinline__ float tanh_acc(float x) {
    return __fdividef(2.0f, 1.0f + __expf(-2.0f * x)) - 1.0f;
}

__global__ void __launch_bounds__(NTHREADS, 1)
grud_kernel(const float* __restrict__ values,
            const float* __restrict__ masks,
            const float* __restrict__ deltas,
            const float* __restrict__ Wtd, const float* __restrict__ btd,
            const float* __restrict__ Wreg, const float* __restrict__ breg,
            const float* __restrict__ Wih, const float* __restrict__ Whh,
            const float* __restrict__ bih, const float* __restrict__ bhh,
            const float* __restrict__ Wout, const float* __restrict__ bout,
            float* __restrict__ out_loss,  // [1]
            float* __restrict__ out_imp,   // [B, T, F]
            float* __restrict__ out_yh)    // [B]
{
    extern __shared__ float smem_raw[];
    Smem& s = *reinterpret_cast<Smem*>(smem_raw);
    const int tid = threadIdx.x;
    const int bb = blockIdx.x * BT;

    // ---- load + transpose weights; load t=0 inputs ----
    for (int i = tid; i < F * HID; i += NTHREADS) {
        int k = i / HID, j = i % HID;
        s.Wtd[k][j] = Wtd[j * F + k];
    }
    for (int i = tid; i < F * HID; i += NTHREADS) {
        int f = i / HID, k = i % HID;
        s.WregT[f][k] = Wreg[f * HID + k];
    }
    for (int i = tid; i < INPD * GATES; i += NTHREADS) {
        int k = i / GATES, j = i % GATES;
        s.Wih[k][j] = Wih[j * INPD + k];
    }
    for (int i = tid; i < HID * GATES; i += NTHREADS) {
        int k = i / GATES, j = i % GATES;
        s.Whh[k][j] = Whh[j * HID + k];
    }
    if (tid < HID) s.btd[tid] = btd[tid];
    if (tid < F)   s.breg[tid] = breg[tid];
    if (tid < GATES) s.bih[tid] = bih[tid] + bhh[tid];
    if (tid < HID) s.Wout[tid] = Wout[tid];
    if (tid == 0)  s.bout = bout[0];
    for (int i = tid; i < BT * HID; i += NTHREADS) {
        s.H[i / HID][i % HID] = 0.0f;
        s.C[i / HID][i % HID] = 0.0f;
    }
    // t=0 inputs into buffer 0
    for (int o = tid; o < BT * F; o += NTHREADS) {
        int r = o / F, f = o % F;
        int base = (bb + r) * (T * F) + f;   // t=0
        float xv = values[base];
        xv = (xv != xv) ? 0.0f : xv;
        s.X[0][r][f] = xv;
        s.M[0][r][f] = masks[base];
        s.D[0][r][f] = deltas[base];
    }
    __syncthreads();

    const int w = tid >> 5;        // warp id 0..15 -> rows r0..r0+3
    const int l = tid & 31;        // lane -> hidden units h0, h0+1
    const int r0 = w * 4;
    const int h0 = l * 2;

    for (int t = 0; t < T; t++) {
        const int cur = t & 1;
        const int nxt = cur ^ 1;

        // ---- prefetch t+1 inputs into registers (overlaps with compute) ----
        float pX[3], pM[3], pD[3];
        const bool pf3 = (tid < BT * F - 2 * NTHREADS);  // 1088 - 1024 = 64
        if (t + 1 < T) {
            #pragma unroll
            for (int j = 0; j < 2; j++) {
                int o = tid + j * NTHREADS;
                int r = o / F, f = o % F;
                int base = (bb + r) * (T * F) + (t + 1) * F + f;
                pX[j] = values[base];
                pM[j] = masks[base];
                pD[j] = deltas[base];
            }
            if (pf3) {
                int o = tid + 2 * NTHREADS;
                int r = o / F, f = o % F;
                int base = (bb + r) * (T * F) + (t + 1) * F + f;
                pX[2] = values[base];
                pM[2] = masks[base];
                pD[2] = deltas[base];
            }
        }

        // ---- phase 2: gamma = exp(-relu(d@Wtd^T + btd)); h *= gamma ----
        {
            float a0[4], a1[4];
            #pragma unroll
            for (int i = 0; i < 4; i++) { a0[i] = s.btd[h0]; a1[i] = s.btd[h0 + 1]; }
            #pragma unroll
            for (int k = 0; k < F; k++) {
                float2 wv = *(const float2*)&s.Wtd[k][h0];
                #pragma unroll
                for (int i = 0; i < 4; i++) {
                    float dv = s.D[cur][r0 + i][k];
                    a0[i] += dv * wv.x;
                    a1[i] += dv * wv.y;
                }
            }
            #pragma unroll
            for (int i = 0; i < 4; i++) {
                float g0 = __expf(-fmaxf(a0[i], 0.0f));
                float g1 = __expf(-fmaxf(a1[i], 0.0f));
                float2* hp = (float2*)&s.H[r0 + i][h0];
                float2 hv = *hp;
                hv.x *= g0; hv.y *= g1;
                *hp = hv;
            }
        }
        __syncthreads();

        // ---- phase 3: x_h, x_c, loss partials, imputation ----
        float lnum = 0.0f, lden = 0.0f;
        for (int o = tid; o < BT * F; o += NTHREADS) {
            int r = o / F, f = o % F;
            float acc = s.breg[f];
            #pragma unroll 8
            for (int k = 0; k < HID; k += 2) {
                float2 h2 = *(const float2*)&s.H[r][k];
                float2 w2 = *(const float2*)&s.WregT[f][k];
                acc += h2.x * w2.x;
                acc += h2.y * w2.y;
            }
            float xv = s.X[cur][r][f];
            float mv = s.M[cur][r][f];
            float xc = mv * xv + (1.0f - mv) * acc;
            s.Inp[r][f] = xc;
            s.Inp[r][F + f] = mv;
            lnum += fabsf(xv - acc) * mv;
            lden += mv;
            out_imp[(bb + r) * (T * F) + t * F + f] = xc;
        }
        #pragma unroll
        for (int ofs = 16; ofs > 0; ofs >>= 1) {
            lnum += __shfl_down_sync(0xFFFFFFFFu, lnum, ofs);
            lden += __shfl_down_sync(0xFFFFFFFFu, lden, ofs);
        }
        if (l == 0) { s.red[w] = lnum; s.red[NW + w] = lden; }
        __syncthreads();
        if (tid == 0) {
            float n = 0.0f, d = 0.0f;
            #pragma unroll
            for (int i = 0; i < NW; i++) { n += s.red[i]; d += s.red[NW + i]; }
            g_num[t * NB + blockIdx.x] = n;
            g_den[t * NB + blockIdx.x] = d;
        }

        // ---- phase 4: gates GEMM + LSTM update ----
        {
            float ai0[4], ai1[4], af0[4], af1[4], ag0[4], ag1[4], ao0[4], ao1[4];
            #pragma unroll
            for (int i = 0; i < 4; i++) {
                ai0[i] = s.bih[h0];           ai1[i] = s.bih[h0 + 1];
                af0[i] = s.bih[64 + h0];      af1[i] = s.bih[64 + h0 + 1];
                ag0[i] = s.bih[128 + h0];     ag1[i] = s.bih[128 + h0 + 1];
                ao0[i] = s.bih[192 + h0];     ao1[i] = s.bih[192 + h0 + 1];
            }
            #pragma unroll 2
            for (int k = 0; k < INPD; k++) {
                float2 wi = *(const float2*)&s.Wih[k][h0];
                float2 wf = *(const float2*)&s.Wih[k][64 + h0];
                float2 wg = *(const float2*)&s.Wih[k][128 + h0];
                float2 wo = *(const float2*)&s.Wih[k][192 + h0];
                #pragma unroll
                for (int i = 0; i < 4; i++) {
                    float v = s.Inp[r0 + i][k];
                    ai0[i] += v * wi.x; ai1[i] += v * wi.y;
                    af0[i] += v * wf.x; af1[i] += v * wf.y;
                    ag0[i] += v * wg.x; ag1[i] += v * wg.y;
                    ao0[i] += v * wo.x; ao1[i] += v * wo.y;
                }
            }
            #pragma unroll 2
            for (int k = 0; k < HID; k++) {
                float2 wi = *(const float2*)&s.Whh[k][h0];
                float2 wf = *(const float2*)&s.Whh[k][64 + h0];
                float2 wg = *(const float2*)&s.Whh[k][128 + h0];
                float2 wo = *(const float2*)&s.Whh[k][192 + h0];
                #pragma unroll
                for (int i = 0; i < 4; i++) {
                    float v = s.H[r0 + i][k];
                    ai0[i] += v * wi.x; ai1[i] += v * wi.y;
                    af0[i] += v * wf.x; af1[i] += v * wf.y;
                    ag0[i] += v * wg.x; ag1[i] += v * wg.y;
                    ao0[i] += v * wo.x; ao1[i] += v * wo.y;
                }
            }
            #pragma unroll
            for (int i = 0; i < 4; i++) {
                float2* cp = (float2*)&s.C[r0 + i][h0];
                float2 cv = *cp;
                float iv0 = sigm(ai0[i]), iv1 = sigm(ai1[i]);
                float fv0 = sigm(af0[i]), fv1 = sigm(af1[i]);
                float gv0 = tanh_acc(ag0[i]), gv1 = tanh_acc(ag1[i]);
                float ov0 = sigm(ao0[i]), ov1 = sigm(ao1[i]);
                float c0 = fv0 * cv.x + iv0 * gv0;
                float c1 = fv1 * cv.y + iv1 * gv1;
                cv.x = c0; cv.y = c1;
                *cp = cv;
                float2* hp = (float2*)&s.H[r0 + i][h0];
                float2 hv;
                hv.x = ov0 * tanh_acc(c0);
                hv.y = ov1 * tanh_acc(c1);
                *hp = hv;
            }
        }

        // ---- store prefetched t+1 inputs ----
        if (t + 1 < T) {
            #pragma unroll
            for (int j = 0; j < 2; j++) {
                int o = tid + j * NTHREADS;
                int r = o / F, f = o % F;
                float xv = pX[j];
                xv = (xv != xv) ? 0.0f : xv;
                s.X[nxt][r][f] = xv;
                s.M[nxt][r][f] = pM[j];
                s.D[nxt][r][f] = pD[j];
            }
            if (pf3) {
                int o = tid + 2 * NTHREADS;
                int r = o / F, f = o % F;
                float xv = pX[2];
                xv = (xv != xv) ? 0.0f : xv;
                s.X[nxt][r][f] = xv;
                s.M[nxt][r][f] = pM[2];
                s.D[nxt][r][f] = pD[2];
            }
        }
        __syncthreads();
    }

    // ---- y_h = h_final @ Wout^T + bout ----
    if (tid < BT) {
        float acc = s.bout;
        #pragma unroll 8
        for (int k = 0; k < HID; k++) acc += s.H[tid][k] * s.Wout[k];
        out_yh[bb + tid] = acc;
    }

    // ---- folded finalize ----
    if (tid == 0) {
        __threadfence();
        unsigned int prev = atomicAdd(&g_cnt, 1u);
        s.flagi = (prev == NB - 1) ? 1 : 0;
    }
    __syncthreads();
    if (s.flagi) {
        __threadfence();
        float v = 0.0f;
        if (tid < T) {
            float n = 0.0f, d = 0.0f;
            for (int b = 0; b < NB; b++) {
                n += g_num[tid * NB + b];
                d += g_den[tid * NB + b];
            }
            v = n / (d + 1e-5f);
        }
        if (tid < 64) s.sv[tid] = v;
        __syncthreads();
        if (tid < 32) {
            float x = s.sv[tid] + s.sv[tid + 32];
            #pragma unroll
            for (int ofs = 16; ofs > 0; ofs >>= 1)
                x += __shfl_down_sync(0xFFFFFFFFu, x, ofs);
            if (tid == 0) {
                out_loss[0] = x;
                g_cnt = 0;
            }
        }
    }
}

extern "C" void kernel_launch(void* const* d_in, const int* in_sizes, int n_in,
                              void* d_out, int out_size) {
    const float* values = (const float*)d_in[0];
    const float* masks  = (const float*)d_in[1];
    const float* deltas = (const float*)d_in[2];
    const float* Wtd    = (const float*)d_in[3];
    const float* btd    = (const float*)d_in[4];
    const float* Wreg   = (const float*)d_in[5];
    const float* breg   = (const float*)d_in[6];
    const float* Wih    = (const float*)d_in[7];
    const float* Whh    = (const float*)d_in[8];
    const float* bih    = (const float*)d_in[9];
    const float* bhh    = (const float*)d_in[10];
    const float* Wout   = (const float*)d_in[11];
    const float* bout   = (const float*)d_in[12];

    float* out = (float*)d_out;
    float* out_loss = out;                       // [1]
    float* out_imp  = out + 1;                   // [B, T, F]
    float* out_yh   = out + 1 + BATCH * T * F;   // [B, 1]

    cudaFuncSetAttribute(grud_kernel,
                         cudaFuncAttributeMaxDynamicSharedMemorySize,
                         (int)sizeof(Smem));
    grud_kernel<<<NB, NTHREADS, sizeof(Smem)>>>(
        values, masks, deltas, Wtd, btd, Wreg, breg,
        Wih, Whh, bih, bhh, Wout, bout, out_loss, out_imp, out_yh);
}

// round 6
// speedup vs baseline: 1.7777x; 1.5698x over previous
#include <cuda_runtime.h>
#include <cuda_bf16.h>

#define BATCH 8192
#define T 50
#define F 17
#define HID 64
#define BT 64
#define NB (BATCH/BT)   // 128 blocks
#define NTHREADS 512
#define NW 16
#define KPAD 112        // 7 k-tiles of 16
#define BSTR 240        // bytes per row of bf16 tiles (120 bf16, 16B aligned)

// k layout of A/B: [xc 0..16][one 17][m 18..34][pad 35][h 36..99][pad 100..111]

typedef unsigned int u32;

__device__ float g_num[T * NB];
__device__ float g_den[T * NB];
__device__ unsigned int g_cnt;

// ---- smem byte offsets ----
#define SM_BHI   0                      // 256*240 = 61440
#define SM_BLO   61440                  // 61440
#define SM_AHI   122880                 // 64*240 = 15360
#define SM_ALO   138240                 // 15360
#define SM_H     153600                 // 64*66*4 = 16896
#define SM_X     170496                 // 64*17*4 = 4352
#define SM_M     174848                 // 4352
#define SM_D     179200                 // 4352
#define SM_WTD   183552                 // 64*17*4 = 4352
#define SM_WREG  187904                 // 17*66*4 = 4488 -> 4496
#define SM_WOUT  192400                 // 256
#define SM_BTD   192656                 // 256
#define SM_BREG  192912                 // 80
#define SM_Y     192992                 // 64*8*4 = 2048
#define SM_RED   195040                 // 128
#define SM_SV    195168                 // 256
#define SM_BOUT  195424                 // 4
#define SM_FLAG  195428                 // 4
#define SM_TOTAL 195456

__device__ __forceinline__ u32 smem_u32(const void* p) {
    u32 a;
    asm("{ .reg .u64 t; cvta.to.shared.u64 t, %1; cvt.u32.u64 %0, t; }" : "=r"(a) : "l"(p));
    return a;
}
__device__ __forceinline__ float sigm(float x) {
    return __fdividef(1.0f, 1.0f + __expf(-x));
}
__device__ __forceinline__ float tanh_acc(float x) {
    return __fdividef(2.0f, 1.0f + __expf(-2.0f * x)) - 1.0f;
}
__device__ __forceinline__ u32 pk_hi(float a, float b) {
    return (u32)__bfloat16_as_ushort(__float2bfloat16(a)) |
           ((u32)__bfloat16_as_ushort(__float2bfloat16(b)) << 16);
}
__device__ __forceinline__ u32 pk_lo(float a, float b) {
    float ra = a - __bfloat162float(__float2bfloat16(a));
    float rb = b - __bfloat162float(__float2bfloat16(b));
    return pk_hi(ra, rb);
}

#define LDSM4(r, addr) \
    asm volatile("ldmatrix.sync.aligned.m8n8.x4.shared.b16 {%0,%1,%2,%3}, [%4];" \
        : "=r"((r)[0]), "=r"((r)[1]), "=r"((r)[2]), "=r"((r)[3]) : "r"(addr))

#define MMA16816(c, a, b0, b1) \
    asm volatile("mma.sync.aligned.m16n8k16.row.col.f32.bf16.bf16.f32 " \
        "{%0,%1,%2,%3}, {%4,%5,%6,%7}, {%8,%9}, {%0,%1,%2,%3};" \
        : "+f"((c)[0]), "+f"((c)[1]), "+f"((c)[2]), "+f"((c)[3]) \
        : "r"((a)[0]), "r"((a)[1]), "r"((a)[2]), "r"((a)[3]), "r"(b0), "r"(b1))

__global__ void __launch_bounds__(NTHREADS, 1)
grud_kernel(const float* __restrict__ values,
            const float* __restrict__ masks,
            const float* __restrict__ deltas,
            const float* __restrict__ Wtd, const float* __restrict__ btd,
            const float* __restrict__ Wreg, const float* __restrict__ breg,
            const float* __restrict__ Wih, const float* __restrict__ Whh,
            const float* __restrict__ bih, const float* __restrict__ bhh,
            const float* __restrict__ Wout, const float* __restrict__ bout,
            float* __restrict__ out_loss,
            float* __restrict__ out_imp,
            float* __restrict__ out_yh)
{
    extern __shared__ __align__(128) char smem[];
    const u32 sbase = smem_u32(smem);
    float* sH    = (float*)(smem + SM_H);     // [64][66]
    float* sX    = (float*)(smem + SM_X);     // [64][17]
    float* sM    = (float*)(smem + SM_M);
    float* sD    = (float*)(smem + SM_D);
    float* sWtd  = (float*)(smem + SM_WTD);   // [64][17]
    float* sWreg = (float*)(smem + SM_WREG);  // [17][66]
    float* sWout = (float*)(smem + SM_WOUT);
    float* sBtd  = (float*)(smem + SM_BTD);
    float* sBreg = (float*)(smem + SM_BREG);
    float* sY    = (float*)(smem + SM_Y);     // [64][8]
    float* sRed  = (float*)(smem + SM_RED);
    float* sSv   = (float*)(smem + SM_SV);
    float* sBout = (float*)(smem + SM_BOUT);
    int*   sFlag = (int*)(smem + SM_FLAG);

    const int tid = threadIdx.x;
    const int wid = tid >> 5;
    const int lid = tid & 31;
    const int wm = wid & 3;              // M tile (16 rows)
    const int wn = wid >> 2;             // N chunk (64 gate-cols)
    const int hsel = (lid & 3) >> 1;     // which hid of the n-tile pair
    const int rpar = lid & 1;            // 0: row g, 1: row g+8
    const int myrow = wm * 16 + (lid >> 2) + rpar * 8;
    const int bb = blockIdx.x * BT;

    // ---- prezero A hi/lo tiles ----
    for (int i = tid; i < (BT * BSTR) / 4; i += NTHREADS) {
        ((u32*)(smem + SM_AHI))[i] = 0u;
        ((u32*)(smem + SM_ALO))[i] = 0u;
    }
    // ---- build B hi/lo tiles: [n][k], n = hid*4 + gate ----
    for (int i = tid; i < 256 * KPAD; i += NTHREADS) {
        int n = i / KPAD, k = i % KPAD;
        int out = (n & 3) * 64 + (n >> 2);
        float w = 0.0f;
        if (k < 17)       w = Wih[out * 34 + k];
        else if (k == 17) w = bih[out] + bhh[out];
        else if (k < 35)  w = Wih[out * 34 + 17 + (k - 18)];
        else if (k >= 36 && k < 100) w = Whh[out * 64 + (k - 36)];
        __nv_bfloat16 whi = __float2bfloat16(w);
        float wlo = w - __bfloat162float(whi);
        *(__nv_bfloat16*)(smem + SM_BHI + n * BSTR + k * 2) = whi;
        *(__nv_bfloat16*)(smem + SM_BLO + n * BSTR + k * 2) = __float2bfloat16(wlo);
    }
    // ---- other weights ----
    for (int i = tid; i < HID * F; i += NTHREADS) sWtd[i] = Wtd[i];
    for (int i = tid; i < F * HID; i += NTHREADS) {
        int f = i / HID, k = i % HID;
        sWreg[f * 66 + k] = Wreg[f * HID + k];
    }
    if (tid < HID) sBtd[tid] = btd[tid];
    if (tid < F)   sBreg[tid] = breg[tid];
    if (tid < HID) sWout[tid] = Wout[tid];
    if (tid == 0)  sBout[0] = bout[0];
    // ones column (k=17) in A hi
    if (tid < BT)
        *(__nv_bfloat16*)(smem + SM_AHI + tid * BSTR + 34) = __float2bfloat16(1.0f);
    // t=0 inputs
    for (int o = tid; o < BT * F; o += NTHREADS) {
        int r = o / F, f = o % F;
        int base = (bb + r) * (T * F) + f;
        float xv = values[base];
        xv = (xv != xv) ? 0.0f : xv;
        sX[r * 17 + f] = xv;
        sM[r * 17 + f] = masks[base];
        sD[r * 17 + f] = deltas[base];
    }
    __syncthreads();

    // ---- ldmatrix lane addresses ----
    const u32 aHiAddr = sbase + SM_AHI +
        (u32)((wm * 16 + (lid & 7) + ((lid >> 3) & 1) * 8) * BSTR + ((lid >> 4) & 1) * 16);
    const u32 aLoAddr = aHiAddr + (SM_ALO - SM_AHI);
    const u32 bHiAddr = sbase + SM_BHI +
        (u32)((wn * 64 + ((lid >> 4) & 1) * 8 + (lid & 7)) * BSTR + ((lid >> 3) & 1) * 16);
    const u32 bLoAddr = bHiAddr + (SM_BLO - SM_BHI);

    float h_reg[8], c_reg[8];
    #pragma unroll
    for (int i = 0; i < 8; i++) { h_reg[i] = 0.0f; c_reg[i] = 0.0f; }

    for (int t = 0; t < T; t++) {
        __syncthreads();   // all warps past previous MMA before touching A

        // ---- prefetch t+1 into registers ----
        float pX[3], pM[3], pD[3];
        const bool pf3 = (tid < BT * F - 2 * NTHREADS);   // 1088-1024=64
        if (t + 1 < T) {
            #pragma unroll
            for (int j = 0; j < 2; j++) {
                int o = tid + j * NTHREADS;
                int r = o / F, f = o % F;
                int base = (bb + r) * (T * F) + (t + 1) * F + f;
                pX[j] = values[base]; pM[j] = masks[base]; pD[j] = deltas[base];
            }
            if (pf3) {
                int o = tid + 2 * NTHREADS;
                int r = o / F, f = o % F;
                int base = (bb + r) * (T * F) + (t + 1) * F + f;
                pX[2] = values[base]; pM[2] = masks[base]; pD[2] = deltas[base];
            }
        }

        // ---- phase 2: gamma, hd = h*gamma -> sH + A h-cols ----
        {
            float dv[F];
            #pragma unroll
            for (int k = 0; k < F; k++) dv[k] = sD[myrow * 17 + k];
            #pragma unroll
            for (int tile = 0; tile < 8; tile++) {
                int hid = wn * 16 + tile * 2 + hsel;
                float acc = sBtd[hid];
                #pragma unroll
                for (int k = 0; k < F; k++) acc += dv[k] * sWtd[hid * 17 + k];
                float gamma = __expf(-fmaxf(acc, 0.0f));
                float hd = h_reg[tile] * gamma;
                sH[myrow * 66 + hid] = hd;
                float hdp = __shfl_xor_sync(0xFFFFFFFFu, hd, 2);
                if (hsel == 0) {
                    int word = 18 + wn * 8 + tile;      // k byte 72 + .. /4
                    *(u32*)(smem + SM_AHI + myrow * BSTR + word * 4) = pk_hi(hd, hdp);
                    *(u32*)(smem + SM_ALO + myrow * BSTR + word * 4) = pk_lo(hd, hdp);
                }
            }
        }
        __syncthreads();   // sH + A h-cols ready

        // ---- phase 3: x_h, x_c, loss, imputations, A xc/m cols ----
        float lnum = 0.0f, lden = 0.0f;
        for (int o = tid; o < BT * F; o += NTHREADS) {
            int r = o / F, f = o % F;
            const float* hp = &sH[r * 66];
            const float* wp = &sWreg[f * 66];
            float a0 = 0.0f, a1 = 0.0f;
            #pragma unroll 8
            for (int k = 0; k < HID; k += 2) {
                float2 h2 = *(const float2*)&hp[k];
                float2 w2 = *(const float2*)&wp[k];
                a0 += h2.x * w2.x;
                a1 += h2.y * w2.y;
            }
            float acc = a0 + a1 + sBreg[f];
            float xv = sX[r * 17 + f];
            float mv = sM[r * 17 + f];
            float xc = mv * xv + (1.0f - mv) * acc;
            __nv_bfloat16 xhi = __float2bfloat16(xc);
            *(__nv_bfloat16*)(smem + SM_AHI + r * BSTR + f * 2) = xhi;
            *(__nv_bfloat16*)(smem + SM_ALO + r * BSTR + f * 2) =
                __float2bfloat16(xc - __bfloat162float(xhi));
            *(__nv_bfloat16*)(smem + SM_AHI + r * BSTR + 36 + f * 2) = __float2bfloat16(mv);
            lnum += fabsf(xv - acc) * mv;
            lden += mv;
            out_imp[(bb + r) * (T * F) + t * F + f] = xc;
        }
        #pragma unroll
        for (int ofs = 16; ofs > 0; ofs >>= 1) {
            lnum += __shfl_down_sync(0xFFFFFFFFu, lnum, ofs);
            lden += __shfl_down_sync(0xFFFFFFFFu, lden, ofs);
        }
        if (lid == 0) { sRed[wid] = lnum; sRed[NW + wid] = lden; }
        __syncthreads();   // A complete, red complete; sX/sM/sD free
        if (tid == 0) {
            float n = 0.0f, d = 0.0f;
            #pragma unroll
            for (int i = 0; i < NW; i++) { n += sRed[i]; d += sRed[NW + i]; }
            g_num[t * NB + blockIdx.x] = n;
            g_den[t * NB + blockIdx.x] = d;
        }

        // ---- store prefetched t+1 inputs (overlaps MMA below) ----
        if (t + 1 < T) {
            #pragma unroll
            for (int j = 0; j < 2; j++) {
                int o = tid + j * NTHREADS;
                int r = o / F, f = o % F;
                float xv = pX[j];
                xv = (xv != xv) ? 0.0f : xv;
                sX[r * 17 + f] = xv; sM[r * 17 + f] = pM[j]; sD[r * 17 + f] = pD[j];
            }
            if (pf3) {
                int o = tid + 2 * NTHREADS;
                int r = o / F, f = o % F;
                float xv = pX[2];
                xv = (xv != xv) ? 0.0f : xv;
                sX[r * 17 + f] = xv; sM[r * 17 + f] = pM[2]; sD[r * 17 + f] = pD[2];
            }
        }

        // ---- gates GEMM: 3x bf16-split HMMA, warp tile m16 x n64 ----
        float cfr[8][4];
        #pragma unroll
        for (int i = 0; i < 8; i++)
            #pragma unroll
            for (int j = 0; j < 4; j++) cfr[i][j] = 0.0f;

        #pragma unroll
        for (int kt = 0; kt < 7; kt++) {
            u32 ah[4], al[4];
            LDSM4(ah, aHiAddr + kt * 32);
            LDSM4(al, aLoAddr + kt * 32);
            #pragma unroll
            for (int np = 0; np < 4; np++) {
                u32 bh[4], bl[4];
                LDSM4(bh, bHiAddr + np * (16 * BSTR) + kt * 32);
                LDSM4(bl, bLoAddr + np * (16 * BSTR) + kt * 32);
                MMA16816(cfr[2 * np],     ah, bh[0], bh[1]);
                MMA16816(cfr[2 * np],     al, bh[0], bh[1]);
                MMA16816(cfr[2 * np],     ah, bl[0], bl[1]);
                MMA16816(cfr[2 * np + 1], ah, bh[2], bh[3]);
                MMA16816(cfr[2 * np + 1], al, bh[2], bh[3]);
                MMA16816(cfr[2 * np + 1], ah, bl[2], bl[3]);
            }
        }

        // ---- epilogue: exchange gate halves, LSTM pointwise ----
        #pragma unroll
        for (int tile = 0; tile < 8; tile++) {
            float e0 = __shfl_xor_sync(0xFFFFFFFFu, cfr[tile][0], 1);
            float e1 = __shfl_xor_sync(0xFFFFFFFFu, cfr[tile][1], 1);
            float e2 = __shfl_xor_sync(0xFFFFFFFFu, cfr[tile][2], 1);
            float e3 = __shfl_xor_sync(0xFFFFFFFFu, cfr[tile][3], 1);
            float gi, gf, gg, go;
            if (rpar == 0) { gi = cfr[tile][0]; gf = cfr[tile][1]; gg = e0; go = e1; }
            else           { gi = e2; gf = e3; gg = cfr[tile][2]; go = cfr[tile][3]; }
            float iv = sigm(gi), fv = sigm(gf);
            float gv = tanh_acc(gg), ov = sigm(go);
            float cc = fv * c_reg[tile] + iv * gv;
            c_reg[tile] = cc;
            h_reg[tile] = ov * tanh_acc(cc);
        }
    }

    // ---- y_h = h_final @ Wout^T + bout ----
    {
        float ph = 0.0f;
        #pragma unroll
        for (int tile = 0; tile < 8; tile++)
            ph += h_reg[tile] * sWout[wn * 16 + tile * 2 + hsel];
        sY[myrow * 8 + wn * 2 + hsel] = ph;
    }
    __syncthreads();
    if (tid < BT) {
        float acc = sBout[0];
        #pragma unroll
        for (int i = 0; i < 8; i++) acc += sY[tid * 8 + i];
        out_yh[bb + tid] = acc;
    }

    // ---- folded finalize ----
    if (tid == 0) {
        __threadfence();
        unsigned int prev = atomicAdd(&g_cnt, 1u);
        sFlag[0] = (prev == NB - 1) ? 1 : 0;
    }
    __syncthreads();
    if (sFlag[0]) {
        __threadfence();
        float v = 0.0f;
        if (tid < T) {
            float n = 0.0f, d = 0.0f;
            for (int b = 0; b < NB; b++) {
                n += g_num[tid * NB + b];
                d += g_den[tid * NB + b];
            }
            v = n / (d + 1e-5f);
        }
        if (tid < 64) sSv[tid] = v;
        __syncthreads();
        if (tid < 32) {
            float x = sSv[tid] + sSv[tid + 32];
            #pragma unroll
            for (int ofs = 16; ofs > 0; ofs >>= 1)
                x += __shfl_down_sync(0xFFFFFFFFu, x, ofs);
            if (tid == 0) {
                out_loss[0] = x;
                g_cnt = 0;
            }
        }
    }
}

extern "C" void kernel_launch(void* const* d_in, const int* in_sizes, int n_in,
                              void* d_out, int out_size) {
    const float* values = (const float*)d_in[0];
    const float* masks  = (const float*)d_in[1];
    const float* deltas = (const float*)d_in[2];
    const float* Wtd    = (const float*)d_in[3];
    const float* btd    = (const float*)d_in[4];
    const float* Wreg   = (const float*)d_in[5];
    const float* breg   = (const float*)d_in[6];
    const float* Wih    = (const float*)d_in[7];
    const float* Whh    = (const float*)d_in[8];
    const float* bih    = (const float*)d_in[9];
    const float* bhh    = (const float*)d_in[10];
    const float* Wout   = (const float*)d_in[11];
    const float* bout   = (const float*)d_in[12];

    float* out = (float*)d_out;
    float* out_loss = out;
    float* out_imp  = out + 1;
    float* out_yh   = out + 1 + BATCH * T * F;

    cudaFuncSetAttribute(grud_kernel,
                         cudaFuncAttributeMaxDynamicSharedMemorySize, SM_TOTAL);
    grud_kernel<<<NB, NTHREADS, SM_TOTAL>>>(
        values, masks, deltas, Wtd, btd, Wreg, breg,
        Wih, Whh, bih, bhh, Wout, bout, out_loss, out_imp, out_yh);
}

// round 7
// speedup vs baseline: 2.3472x; 1.3204x over previous
#include <cuda_runtime.h>
#include <cuda_bf16.h>

#define BATCH 8192
#define T 50
#define F 17
#define HID 64
#define BT 64
#define NB (BATCH/BT)   // 128 blocks
#define NTHREADS 512
#define NW 16
#define KPAD 112        // 7 k-tiles of 16
#define BSTR 240        // bytes per bf16-tile row (120 bf16; 16B-aligned, LDSM conflict-free)

// k layout of A / gates-B: [h 0..63][xc 64..80][one 81][m 82..98][pad 99..111]

typedef unsigned int u32;

__device__ float g_num[T * NB];
__device__ float g_den[T * NB];
__device__ unsigned int g_cnt;

// ---- smem byte offsets ----
#define SM_BHI   0                      // 256*240 = 61440
#define SM_BLO   61440
#define SM_AHI   122880                 // 64*240 = 15360
#define SM_ALO   138240
#define SM_WRGH  153600                 // 24*144 = 3456 (Wreg^T hi)
#define SM_WRGL  157056                 // 3456
#define SM_X     160512                 // 64*17*4 = 4352
#define SM_M     164864
#define SM_D     169216
#define SM_WTD   173568                 // 64*17*4 = 4352
#define SM_WOUT  177920                 // 256
#define SM_BTD   178176                 // 256
#define SM_BREG  178432                 // 80
#define SM_Y     178512                 // 64*8*4 = 2048
#define SM_RED   180560                 // 128
#define SM_SV    180688                 // 256
#define SM_BOUT  180944
#define SM_FLAG  180948
#define SM_TOTAL 180992

__device__ __forceinline__ u32 smem_u32(const void* p) {
    u32 a;
    asm("{ .reg .u64 t; cvta.to.shared.u64 t, %1; cvt.u32.u64 %0, t; }" : "=r"(a) : "l"(p));
    return a;
}
__device__ __forceinline__ float sigm(float x) {
    return __fdividef(1.0f, 1.0f + __expf(-x));
}
__device__ __forceinline__ float tanh_acc(float x) {
    return __fdividef(2.0f, 1.0f + __expf(-2.0f * x)) - 1.0f;
}
__device__ __forceinline__ u32 pk_hi(float a, float b) {
    return (u32)__bfloat16_as_ushort(__float2bfloat16(a)) |
           ((u32)__bfloat16_as_ushort(__float2bfloat16(b)) << 16);
}
__device__ __forceinline__ u32 pk_lo(float a, float b) {
    float ra = a - __bfloat162float(__float2bfloat16(a));
    float rb = b - __bfloat162float(__float2bfloat16(b));
    return pk_hi(ra, rb);
}

#define LDSM4(r, addr) \
    asm volatile("ldmatrix.sync.aligned.m8n8.x4.shared.b16 {%0,%1,%2,%3}, [%4];" \
        : "=r"((r)[0]), "=r"((r)[1]), "=r"((r)[2]), "=r"((r)[3]) : "r"(addr))
#define LDSM2(r, addr) \
    asm volatile("ldmatrix.sync.aligned.m8n8.x2.shared.b16 {%0,%1}, [%2];" \
        : "=r"((r)[0]), "=r"((r)[1]) : "r"(addr))

#define MMA16816(c, a, b0, b1) \
    asm volatile("mma.sync.aligned.m16n8k16.row.col.f32.bf16.bf16.f32 " \
        "{%0,%1,%2,%3}, {%4,%5,%6,%7}, {%8,%9}, {%0,%1,%2,%3};" \
        : "+f"((c)[0]), "+f"((c)[1]), "+f"((c)[2]), "+f"((c)[3]) \
        : "r"((a)[0]), "r"((a)[1]), "r"((a)[2]), "r"((a)[3]), "r"(b0), "r"(b1))

__global__ void __launch_bounds__(NTHREADS, 1)
grud_kernel(const float* __restrict__ values,
            const float* __restrict__ masks,
            const float* __restrict__ deltas,
            const float* __restrict__ Wtd, const float* __restrict__ btd,
            const float* __restrict__ Wreg, const float* __restrict__ breg,
            const float* __restrict__ Wih, const float* __restrict__ Whh,
            const float* __restrict__ bih, const float* __restrict__ bhh,
            const float* __restrict__ Wout, const float* __restrict__ bout,
            float* __restrict__ out_loss,
            float* __restrict__ out_imp,
            float* __restrict__ out_yh)
{
    extern __shared__ __align__(128) char smem[];
    const u32 sbase = smem_u32(smem);
    float* sX    = (float*)(smem + SM_X);     // [64][17]
    float* sM    = (float*)(smem + SM_M);
    float* sD    = (float*)(smem + SM_D);
    float* sWtd  = (float*)(smem + SM_WTD);   // [64][17]
    float* sWout = (float*)(smem + SM_WOUT);
    float* sBtd  = (float*)(smem + SM_BTD);
    float* sBreg = (float*)(smem + SM_BREG);
    float* sY    = (float*)(smem + SM_Y);     // [64][8]
    float* sRed  = (float*)(smem + SM_RED);
    float* sSv   = (float*)(smem + SM_SV);
    float* sBout = (float*)(smem + SM_BOUT);
    int*   sFlag = (int*)(smem + SM_FLAG);

    const int tid = threadIdx.x;
    const int wid = tid >> 5;
    const int lid = tid & 31;
    const int wm = wid & 3;              // M tile (16 rows)
    const int wn = wid >> 2;             // N chunk (64 gate-cols / 8 x_h-cols)
    const int hsel = (lid & 3) >> 1;
    const int rpar = lid & 1;
    const int myrow = wm * 16 + (lid >> 2) + rpar * 8;
    const int bb = blockIdx.x * BT;

    // ---- prezero A hi/lo tiles and Wreg tiles ----
    for (int i = tid; i < (BT * BSTR) / 4; i += NTHREADS) {
        ((u32*)(smem + SM_AHI))[i] = 0u;
        ((u32*)(smem + SM_ALO))[i] = 0u;
    }
    for (int i = tid; i < (24 * 144) / 4; i += NTHREADS) {
        ((u32*)(smem + SM_WRGH))[i] = 0u;
        ((u32*)(smem + SM_WRGL))[i] = 0u;
    }
    // ---- build gates B hi/lo tiles: [n][k], n = hid*4 + gate ----
    for (int i = tid; i < 256 * KPAD; i += NTHREADS) {
        int n = i / KPAD, k = i % KPAD;
        int out = (n & 3) * 64 + (n >> 2);
        float w = 0.0f;
        if (k < 64)       w = Whh[out * 64 + k];
        else if (k < 81)  w = Wih[out * 34 + (k - 64)];
        else if (k == 81) w = bih[out] + bhh[out];
        else if (k < 99)  w = Wih[out * 34 + 17 + (k - 82)];
        __nv_bfloat16 whi = __float2bfloat16(w);
        float wlo = w - __bfloat162float(whi);
        *(__nv_bfloat16*)(smem + SM_BHI + n * BSTR + k * 2) = whi;
        *(__nv_bfloat16*)(smem + SM_BLO + n * BSTR + k * 2) = __float2bfloat16(wlo);
    }
    __syncthreads();   // prezero visible before Wreg scatter
    // ---- Wreg^T hi/lo tile [f][k] ----
    for (int i = tid; i < F * HID; i += NTHREADS) {
        int f = i / HID, k = i % HID;
        float w = Wreg[f * HID + k];
        __nv_bfloat16 whi = __float2bfloat16(w);
        *(__nv_bfloat16*)(smem + SM_WRGH + f * 144 + k * 2) = whi;
        *(__nv_bfloat16*)(smem + SM_WRGL + f * 144 + k * 2) =
            __float2bfloat16(w - __bfloat162float(whi));
    }
    for (int i = tid; i < HID * F; i += NTHREADS) sWtd[i] = Wtd[i];
    if (tid < HID) sBtd[tid] = btd[tid];
    if (tid < F)   sBreg[tid] = breg[tid];
    if (tid < HID) sWout[tid] = Wout[tid];
    if (tid == 0)  sBout[0] = bout[0];
    // ones column (k=81 -> byte 162) in A hi
    if (tid < BT)
        *(__nv_bfloat16*)(smem + SM_AHI + tid * BSTR + 162) = __float2bfloat16(1.0f);
    // t=0 inputs
    for (int o = tid; o < BT * F; o += NTHREADS) {
        int r = o / F, f = o % F;
        int base = (bb + r) * (T * F) + f;
        float xv = values[base];
        xv = (xv != xv) ? 0.0f : xv;
        sX[r * 17 + f] = xv;
        sM[r * 17 + f] = masks[base];
        sD[r * 17 + f] = deltas[base];
    }
    __syncthreads();

    // ---- ldmatrix lane addresses ----
    const u32 aHiAddr = sbase + SM_AHI +
        (u32)((wm * 16 + (lid & 7) + ((lid >> 3) & 1) * 8) * BSTR + ((lid >> 4) & 1) * 16);
    const u32 aLoAddr = aHiAddr + (SM_ALO - SM_AHI);
    const u32 bHiAddr = sbase + SM_BHI +
        (u32)((wn * 64 + ((lid >> 4) & 1) * 8 + (lid & 7)) * BSTR + ((lid >> 3) & 1) * 16);
    const u32 bLoAddr = bHiAddr + (SM_BLO - SM_BHI);
    const u32 wrgHAddr = sbase + SM_WRGH +
        (u32)((wn * 8 + (lid & 7)) * 144 + ((lid >> 3) & 1) * 16);
    const u32 wrgLAddr = wrgHAddr + (SM_WRGL - SM_WRGH);

    float h_reg[8], c_reg[8];
    #pragma unroll
    for (int i = 0; i < 8; i++) { h_reg[i] = 0.0f; c_reg[i] = 0.0f; }

    for (int t = 0; t < T; t++) {
        __syncthreads();   // prev gates LDSM done before A rewrite; sX/sM/sD stores visible

        // ---- prefetch t+1 into registers ----
        float pX[3], pM[3], pD[3];
        const bool pf3 = (tid < BT * F - 2 * NTHREADS);
        if (t + 1 < T) {
            #pragma unroll
            for (int j = 0; j < 2; j++) {
                int o = tid + j * NTHREADS;
                int r = o / F, f = o % F;
                int base = (bb + r) * (T * F) + (t + 1) * F + f;
                pX[j] = values[base]; pM[j] = masks[base]; pD[j] = deltas[base];
            }
            if (pf3) {
                int o = tid + 2 * NTHREADS;
                int r = o / F, f = o % F;
                int base = (bb + r) * (T * F) + (t + 1) * F + f;
                pX[2] = values[base]; pM[2] = masks[base]; pD[2] = deltas[base];
            }
        }

        // ---- phase 2: gamma, hd = h*gamma -> A h-cols (k 0..63) ----
        {
            float dv[F];
            #pragma unroll
            for (int k = 0; k < F; k++) dv[k] = sD[myrow * 17 + k];
            #pragma unroll
            for (int tile = 0; tile < 8; tile++) {
                int hid = wn * 16 + tile * 2 + hsel;
                float acc = sBtd[hid];
                #pragma unroll
                for (int k = 0; k < F; k++) acc += dv[k] * sWtd[hid * 17 + k];
                float gamma = __expf(-fmaxf(acc, 0.0f));
                float hd = h_reg[tile] * gamma;
                float hdp = __shfl_xor_sync(0xFFFFFFFFu, hd, 2);
                if (hsel == 0) {
                    int word = wn * 8 + tile;   // hid pair -> k word
                    *(u32*)(smem + SM_AHI + myrow * BSTR + word * 4) = pk_hi(hd, hdp);
                    *(u32*)(smem + SM_ALO + myrow * BSTR + word * 4) = pk_lo(hd, hdp);
                }
            }
        }
        __syncthreads();   // A h-cols ready

        // ---- x_h MMA (warps wn<3) / m-col writes (wn==3) ----
        float lnum = 0.0f, lden = 0.0f;
        if (wn < 3) {
            float cx[4] = {0.0f, 0.0f, 0.0f, 0.0f};
            #pragma unroll
            for (int kt = 0; kt < 4; kt++) {
                u32 ah[4], al[4], bh[2], bl[2];
                LDSM4(ah, aHiAddr + kt * 32);
                LDSM4(al, aLoAddr + kt * 32);
                LDSM2(bh, wrgHAddr + kt * 32);
                LDSM2(bl, wrgLAddr + kt * 32);
                MMA16816(cx, ah, bh[0], bh[1]);
                MMA16816(cx, al, bh[0], bh[1]);
                MMA16816(cx, ah, bl[0], bl[1]);
            }
            // epilogue: xc, loss, imputation, write A xc-cols (k 64..80)
            int f0 = wn * 8 + (lid & 3) * 2;
            if (f0 < 17) {
                #pragma unroll
                for (int half = 0; half < 2; half++) {
                    int r = wm * 16 + (lid >> 2) + half * 8;
                    float acc0 = cx[2 * half] + sBreg[f0];
                    float xv0 = sX[r * 17 + f0];
                    float mv0 = sM[r * 17 + f0];
                    float xc0 = mv0 * xv0 + (1.0f - mv0) * acc0;
                    lnum += fabsf(xv0 - acc0) * mv0;
                    lden += mv0;
                    out_imp[(bb + r) * (T * F) + t * F + f0] = xc0;
                    if (f0 < 16) {
                        float acc1 = cx[2 * half + 1] + sBreg[f0 + 1];
                        float xv1 = sX[r * 17 + f0 + 1];
                        float mv1 = sM[r * 17 + f0 + 1];
                        float xc1 = mv1 * xv1 + (1.0f - mv1) * acc1;
                        lnum += fabsf(xv1 - acc1) * mv1;
                        lden += mv1;
                        out_imp[(bb + r) * (T * F) + t * F + f0 + 1] = xc1;
                        *(u32*)(smem + SM_AHI + r * BSTR + 128 + 2 * f0) = pk_hi(xc0, xc1);
                        *(u32*)(smem + SM_ALO + r * BSTR + 128 + 2 * f0) = pk_lo(xc0, xc1);
                    } else {  // f0 == 16: single element (byte 162 is the ones col!)
                        __nv_bfloat16 xhi = __float2bfloat16(xc0);
                        *(__nv_bfloat16*)(smem + SM_AHI + r * BSTR + 128 + 2 * f0) = xhi;
                        *(__nv_bfloat16*)(smem + SM_ALO + r * BSTR + 128 + 2 * f0) =
                            __float2bfloat16(xc0 - __bfloat162float(xhi));
                    }
                }
            }
        } else {
            // m columns (k 82..98 -> byte 164+2f), bf16-exact
            int row = wm * 16 + (lid >> 1);
            for (int f = (lid & 1); f < 17; f += 2) {
                *(__nv_bfloat16*)(smem + SM_AHI + row * BSTR + 164 + 2 * f) =
                    __float2bfloat16(sM[row * 17 + f]);
            }
        }
        #pragma unroll
        for (int ofs = 16; ofs > 0; ofs >>= 1) {
            lnum += __shfl_down_sync(0xFFFFFFFFu, lnum, ofs);
            lden += __shfl_down_sync(0xFFFFFFFFu, lden, ofs);
        }
        if (lid == 0) { sRed[wid] = lnum; sRed[NW + wid] = lden; }
        __syncthreads();   // A complete (xc+m), sRed ready
        if (tid == 0) {
            float n = 0.0f, d = 0.0f;
            #pragma unroll
            for (int i = 0; i < NW; i++) { n += sRed[i]; d += sRed[NW + i]; }
            g_num[t * NB + blockIdx.x] = n;
            g_den[t * NB + blockIdx.x] = d;
        }

        // ---- store prefetched t+1 inputs (overlaps gates MMA) ----
        if (t + 1 < T) {
            #pragma unroll
            for (int j = 0; j < 2; j++) {
                int o = tid + j * NTHREADS;
                int r = o / F, f = o % F;
                float xv = pX[j];
                xv = (xv != xv) ? 0.0f : xv;
                sX[r * 17 + f] = xv; sM[r * 17 + f] = pM[j]; sD[r * 17 + f] = pD[j];
            }
            if (pf3) {
                int o = tid + 2 * NTHREADS;
                int r = o / F, f = o % F;
                float xv = pX[2];
                xv = (xv != xv) ? 0.0f : xv;
                sX[r * 17 + f] = xv; sM[r * 17 + f] = pM[2]; sD[r * 17 + f] = pD[2];
            }
        }

        // ---- gates GEMM: 3x bf16-split HMMA, warp tile m16 x n64 ----
        float cfr[8][4];
        #pragma unroll
        for (int i = 0; i < 8; i++)
            #pragma unroll
            for (int j = 0; j < 4; j++) cfr[i][j] = 0.0f;

        #pragma unroll
        for (int kt = 0; kt < 7; kt++) {
            u32 ah[4], al[4];
            LDSM4(ah, aHiAddr + kt * 32);
            LDSM4(al, aLoAddr + kt * 32);
            #pragma unroll
            for (int np = 0; np < 4; np++) {
                u32 bh[4], bl[4];
                LDSM4(bh, bHiAddr + np * (16 * BSTR) + kt * 32);
                LDSM4(bl, bLoAddr + np * (16 * BSTR) + kt * 32);
                MMA16816(cfr[2 * np],     ah, bh[0], bh[1]);
                MMA16816(cfr[2 * np],     al, bh[0], bh[1]);
                MMA16816(cfr[2 * np],     ah, bl[0], bl[1]);
                MMA16816(cfr[2 * np + 1], ah, bh[2], bh[3]);
                MMA16816(cfr[2 * np + 1], al, bh[2], bh[3]);
                MMA16816(cfr[2 * np + 1], ah, bl[2], bl[3]);
            }
        }

        // ---- epilogue: exchange gate halves, LSTM pointwise ----
        #pragma unroll
        for (int tile = 0; tile < 8; tile++) {
            float e0 = __shfl_xor_sync(0xFFFFFFFFu, cfr[tile][0], 1);
            float e1 = __shfl_xor_sync(0xFFFFFFFFu, cfr[tile][1], 1);
            float e2 = __shfl_xor_sync(0xFFFFFFFFu, cfr[tile][2], 1);
            float e3 = __shfl_xor_sync(0xFFFFFFFFu, cfr[tile][3], 1);
            float gi, gf, gg, go;
            if (rpar == 0) { gi = cfr[tile][0]; gf = cfr[tile][1]; gg = e0; go = e1; }
            else           { gi = e2; gf = e3; gg = cfr[tile][2]; go = cfr[tile][3]; }
            float iv = sigm(gi), fv = sigm(gf);
            float gv = tanh_acc(gg), ov = sigm(go);
            float cc = fv * c_reg[tile] + iv * gv;
            c_reg[tile] = cc;
            h_reg[tile] = ov * tanh_acc(cc);
        }
    }

    // ---- y_h = h_final @ Wout^T + bout ----
    {
        float ph = 0.0f;
        #pragma unroll
        for (int tile = 0; tile < 8; tile++)
            ph += h_reg[tile] * sWout[wn * 16 + tile * 2 + hsel];
        sY[myrow * 8 + wn * 2 + hsel] = ph;
    }
    __syncthreads();
    if (tid < BT) {
        float acc = sBout[0];
        #pragma unroll
        for (int i = 0; i < 8; i++) acc += sY[tid * 8 + i];
        out_yh[bb + tid] = acc;
    }

    // ---- folded finalize ----
    if (tid == 0) {
        __threadfence();
        unsigned int prev = atomicAdd(&g_cnt, 1u);
        sFlag[0] = (prev == NB - 1) ? 1 : 0;
    }
    __syncthreads();
    if (sFlag[0]) {
        __threadfence();
        float v = 0.0f;
        if (tid < T) {
            float n = 0.0f, d = 0.0f;
            for (int b = 0; b < NB; b++) {
                n += g_num[tid * NB + b];
                d += g_den[tid * NB + b];
            }
            v = n / (d + 1e-5f);
        }
        if (tid < 64) sSv[tid] = v;
        __syncthreads();
        if (tid < 32) {
            float x = sSv[tid] + sSv[tid + 32];
            #pragma unroll
            for (int ofs = 16; ofs > 0; ofs >>= 1)
                x += __shfl_down_sync(0xFFFFFFFFu, x, ofs);
            if (tid == 0) {
                out_loss[0] = x;
                g_cnt = 0;
            }
        }
    }
}

extern "C" void kernel_launch(void* const* d_in, const int* in_sizes, int n_in,
                              void* d_out, int out_size) {
    const float* values = (const float*)d_in[0];
    const float* masks  = (const float*)d_in[1];
    const float* deltas = (const float*)d_in[2];
    const float* Wtd    = (const float*)d_in[3];
    const float* btd    = (const float*)d_in[4];
    const float* Wreg   = (const float*)d_in[5];
    const float* breg   = (const float*)d_in[6];
    const float* Wih    = (const float*)d_in[7];
    const float* Whh    = (const float*)d_in[8];
    const float* bih    = (const float*)d_in[9];
    const float* bhh    = (const float*)d_in[10];
    const float* Wout   = (const float*)d_in[11];
    const float* bout   = (const float*)d_in[12];

    float* out = (float*)d_out;
    float* out_loss = out;
    float* out_imp  = out + 1;
    float* out_yh   = out + 1 + BATCH * T * F;

    cudaFuncSetAttribute(grud_kernel,
                         cudaFuncAttributeMaxDynamicSharedMemorySize, SM_TOTAL);
    grud_kernel<<<NB, NTHREADS, SM_TOTAL>>>(
        values, masks, deltas, Wtd, btd, Wreg, breg,
        Wih, Whh, bih, bhh, Wout, bout, out_loss, out_imp, out_yh);
}

// round 8
// speedup vs baseline: 2.6256x; 1.1186x over previous
#include <cuda_runtime.h>
#include <cuda_bf16.h>

#define BATCH 8192
#define T 50
#define F 17
#define HID 64
#define BT 64
#define NB (BATCH/BT)   // 128 blocks
#define NTHREADS 512
#define NW 16
#define KPAD 112        // 7 k-tiles of 16
#define BSTR 240        // bytes per bf16-tile row

// k layout of A / gates-B: [h 0..63][xc 64..80][one 81][m 82..98][pad 99..111]

typedef unsigned int u32;

__device__ float g_num[T * NB];
__device__ float g_den[T * NB];
__device__ unsigned int g_cnt;

// ---- smem byte offsets ----
#define SM_BHI   0                      // 256*240 = 61440
#define SM_BLO   61440
#define SM_AHI   122880                 // 64*240 = 15360
#define SM_ALO   138240
#define SM_WRGH  153600                 // 24*144 = 3456 (Wreg^T hi)
#define SM_WRGL  157056
#define SM_X     160512                 // 64*17*4 = 4352
#define SM_M     164864
#define SM_D     169216
#define SM_WTD   173568                 // 64*17*4 = 4352
#define SM_WOUT  177920
#define SM_BTD   178176
#define SM_BREG  178432
#define SM_Y     178512                 // 64*8*4 = 2048
#define SM_RED   180560
#define SM_SV    180688
#define SM_BOUT  180944
#define SM_FLAG  180948
#define SM_TOTAL 180992

__device__ __forceinline__ u32 smem_u32(const void* p) {
    u32 a;
    asm("{ .reg .u64 t; cvta.to.shared.u64 t, %1; cvt.u32.u64 %0, t; }" : "=r"(a) : "l"(p));
    return a;
}
__device__ __forceinline__ float tanhax(float x) {
    float r;
    asm("tanh.approx.f32 %0, %1;" : "=f"(r) : "f"(x));
    return r;
}
__device__ __forceinline__ float sigm(float x) {
    return fmaf(0.5f, tanhax(0.5f * x), 0.5f);
}
__device__ __forceinline__ u32 pk_hi(float a, float b) {
    return (u32)__bfloat16_as_ushort(__float2bfloat16(a)) |
           ((u32)__bfloat16_as_ushort(__float2bfloat16(b)) << 16);
}
__device__ __forceinline__ u32 pk_lo(float a, float b) {
    float ra = a - __bfloat162float(__float2bfloat16(a));
    float rb = b - __bfloat162float(__float2bfloat16(b));
    return pk_hi(ra, rb);
}

#define LDSM4(r, addr) \
    asm volatile("ldmatrix.sync.aligned.m8n8.x4.shared.b16 {%0,%1,%2,%3}, [%4];" \
        : "=r"((r)[0]), "=r"((r)[1]), "=r"((r)[2]), "=r"((r)[3]) : "r"(addr))
#define LDSM2(r, addr) \
    asm volatile("ldmatrix.sync.aligned.m8n8.x2.shared.b16 {%0,%1}, [%2];" \
        : "=r"((r)[0]), "=r"((r)[1]) : "r"(addr))

#define MMA16816(c, a, b0, b1) \
    asm volatile("mma.sync.aligned.m16n8k16.row.col.f32.bf16.bf16.f32 " \
        "{%0,%1,%2,%3}, {%4,%5,%6,%7}, {%8,%9}, {%0,%1,%2,%3};" \
        : "+f"((c)[0]), "+f"((c)[1]), "+f"((c)[2]), "+f"((c)[3]) \
        : "r"((a)[0]), "r"((a)[1]), "r"((a)[2]), "r"((a)[3]), "r"(b0), "r"(b1))

__global__ void __launch_bounds__(NTHREADS, 1)
grud_kernel(const float* __restrict__ values,
            const float* __restrict__ masks,
            const float* __restrict__ deltas,
            const float* __restrict__ Wtd, const float* __restrict__ btd,
            const float* __restrict__ Wreg, const float* __restrict__ breg,
            const float* __restrict__ Wih, const float* __restrict__ Whh,
            const float* __restrict__ bih, const float* __restrict__ bhh,
            const float* __restrict__ Wout, const float* __restrict__ bout,
            float* __restrict__ out_loss,
            float* __restrict__ out_imp,
            float* __restrict__ out_yh)
{
    extern __shared__ __align__(128) char smem[];
    const u32 sbase = smem_u32(smem);
    float* sX    = (float*)(smem + SM_X);     // [64][17]
    float* sM    = (float*)(smem + SM_M);
    float* sD    = (float*)(smem + SM_D);
    float* sWtd  = (float*)(smem + SM_WTD);   // [64][17]
    float* sWout = (float*)(smem + SM_WOUT);
    float* sBtd  = (float*)(smem + SM_BTD);
    float* sBreg = (float*)(smem + SM_BREG);
    float* sY    = (float*)(smem + SM_Y);     // [64][8]
    float* sRed  = (float*)(smem + SM_RED);
    float* sSv   = (float*)(smem + SM_SV);
    float* sBout = (float*)(smem + SM_BOUT);
    int*   sFlag = (int*)(smem + SM_FLAG);

    const int tid = threadIdx.x;
    const int wid = tid >> 5;
    const int lid = tid & 31;
    const int wm = wid & 3;              // M tile (16 rows)
    const int wn = wid >> 2;             // N chunk
    const int hsel = (lid & 3) >> 1;
    const int rpar = lid & 1;
    const int myrow = wm * 16 + (lid >> 2) + rpar * 8;
    const int bb = blockIdx.x * BT;

    // ---- prezero A hi/lo tiles and Wreg tiles ----
    for (int i = tid; i < (BT * BSTR) / 4; i += NTHREADS) {
        ((u32*)(smem + SM_AHI))[i] = 0u;
        ((u32*)(smem + SM_ALO))[i] = 0u;
    }
    for (int i = tid; i < (24 * 144) / 4; i += NTHREADS) {
        ((u32*)(smem + SM_WRGH))[i] = 0u;
        ((u32*)(smem + SM_WRGL))[i] = 0u;
    }
    // ---- build gates B hi/lo tiles: [n][k], n = hid*4 + gate ----
    for (int i = tid; i < 256 * KPAD; i += NTHREADS) {
        int n = i / KPAD, k = i % KPAD;
        int out = (n & 3) * 64 + (n >> 2);
        float w = 0.0f;
        if (k < 64)       w = Whh[out * 64 + k];
        else if (k < 81)  w = Wih[out * 34 + (k - 64)];
        else if (k == 81) w = bih[out] + bhh[out];
        else if (k < 99)  w = Wih[out * 34 + 17 + (k - 82)];
        __nv_bfloat16 whi = __float2bfloat16(w);
        float wlo = w - __bfloat162float(whi);
        *(__nv_bfloat16*)(smem + SM_BHI + n * BSTR + k * 2) = whi;
        *(__nv_bfloat16*)(smem + SM_BLO + n * BSTR + k * 2) = __float2bfloat16(wlo);
    }
    __syncthreads();
    // ---- Wreg^T hi/lo tile [f][k] ----
    for (int i = tid; i < F * HID; i += NTHREADS) {
        int f = i / HID, k = i % HID;
        float w = Wreg[f * HID + k];
        __nv_bfloat16 whi = __float2bfloat16(w);
        *(__nv_bfloat16*)(smem + SM_WRGH + f * 144 + k * 2) = whi;
        *(__nv_bfloat16*)(smem + SM_WRGL + f * 144 + k * 2) =
            __float2bfloat16(w - __bfloat162float(whi));
    }
    for (int i = tid; i < HID * F; i += NTHREADS) sWtd[i] = Wtd[i];
    if (tid < HID) sBtd[tid] = btd[tid];
    if (tid < F)   sBreg[tid] = breg[tid];
    if (tid < HID) sWout[tid] = Wout[tid];
    if (tid == 0)  sBout[0] = bout[0];
    if (tid < BT)
        *(__nv_bfloat16*)(smem + SM_AHI + tid * BSTR + 162) = __float2bfloat16(1.0f);
    // t=0 inputs
    for (int o = tid; o < BT * F; o += NTHREADS) {
        int r = o / F, f = o % F;
        int base = (bb + r) * (T * F) + f;
        float xv = values[base];
        xv = (xv != xv) ? 0.0f : xv;
        sX[r * 17 + f] = xv;
        sM[r * 17 + f] = masks[base];
        sD[r * 17 + f] = deltas[base];
    }
    __syncthreads();

    // ---- ldmatrix lane addresses ----
    const u32 aHiAddr = sbase + SM_AHI +
        (u32)((wm * 16 + (lid & 7) + ((lid >> 3) & 1) * 8) * BSTR + ((lid >> 4) & 1) * 16);
    const u32 aLoAddr = aHiAddr + (SM_ALO - SM_AHI);
    const u32 bHiAddr = sbase + SM_BHI +
        (u32)((wn * 64 + ((lid >> 4) & 1) * 8 + (lid & 7)) * BSTR + ((lid >> 3) & 1) * 16);
    const u32 bLoAddr = bHiAddr + (SM_BLO - SM_BHI);
    const u32 wrgHAddr = sbase + SM_WRGH +
        (u32)((wn * 8 + (lid & 7)) * 144 + ((lid >> 3) & 1) * 16);
    const u32 wrgLAddr = wrgHAddr + (SM_WRGL - SM_WRGH);

    // ---- hoisted prefetch indices ----
    int prR[3], prF[3], prB[3];
    {
        #pragma unroll
        for (int j = 0; j < 3; j++) {
            int o = tid + j * NTHREADS;
            int r = o / F, f = o - r * F;
            prR[j] = r; prF[j] = f;
            prB[j] = (bb + r) * (T * F) + f;
        }
    }
    const bool pf3 = (tid < BT * F - 2 * NTHREADS);

    float h_reg[8], c_reg[8];
    #pragma unroll
    for (int i = 0; i < 8; i++) { h_reg[i] = 0.0f; c_reg[i] = 0.0f; }

    for (int t = 0; t < T; t++) {
        __syncthreads();   // prev LDSM done before A rewrite; prefetch stores visible

        // ---- prefetch t+1 into registers ----
        float pX[3], pM[3], pD[3];
        if (t + 1 < T) {
            #pragma unroll
            for (int j = 0; j < 2; j++) {
                int base = prB[j] + (t + 1) * F;
                pX[j] = values[base]; pM[j] = masks[base]; pD[j] = deltas[base];
            }
            if (pf3) {
                int base = prB[2] + (t + 1) * F;
                pX[2] = values[base]; pM[2] = masks[base]; pD[2] = deltas[base];
            }
        }

        // ---- phase 2: gamma, hd = h*gamma -> A h-cols (k 0..63) ----
        {
            float dv[F];
            #pragma unroll
            for (int k = 0; k < F; k++) dv[k] = sD[myrow * 17 + k];
            #pragma unroll
            for (int tile = 0; tile < 8; tile++) {
                int hid = wn * 16 + tile * 2 + hsel;
                float acc = sBtd[hid];
                #pragma unroll
                for (int k = 0; k < F; k++) acc += dv[k] * sWtd[hid * 17 + k];
                float gamma = __expf(-fmaxf(acc, 0.0f));
                float hd = h_reg[tile] * gamma;
                float hdp = __shfl_xor_sync(0xFFFFFFFFu, hd, 2);
                if (hsel == 0) {
                    int word = wn * 8 + tile;
                    *(u32*)(smem + SM_AHI + myrow * BSTR + word * 4) = pk_hi(hd, hdp);
                    *(u32*)(smem + SM_ALO + myrow * BSTR + word * 4) = pk_lo(hd, hdp);
                }
            }
        }
        __syncthreads();   // A h-cols ready

        // ==== phase A: x_h MMA (wn<3) / m-cols (wn==3), PLUS gates kt0..3 (all) ====
        float cfr[8][4];
        #pragma unroll
        for (int i = 0; i < 8; i++)
            #pragma unroll
            for (int j = 0; j < 4; j++) cfr[i][j] = 0.0f;

        float lnum = 0.0f, lden = 0.0f;
        float cx[4] = {0.0f, 0.0f, 0.0f, 0.0f};

        if (wn < 3) {
            // x_h MMA over h k-tiles 0..3
            #pragma unroll
            for (int kt = 0; kt < 4; kt++) {
                u32 ah[4], al[4], bh[2], bl[2];
                LDSM4(ah, aHiAddr + kt * 32);
                LDSM4(al, aLoAddr + kt * 32);
                LDSM2(bh, wrgHAddr + kt * 32);
                LDSM2(bl, wrgLAddr + kt * 32);
                MMA16816(cx, ah, bh[0], bh[1]);
                MMA16816(cx, al, bh[0], bh[1]);
                MMA16816(cx, ah, bl[0], bl[1]);
            }
        } else {
            // m columns (k 82..98 -> byte 164+2f)
            int row = wm * 16 + (lid >> 1);
            #pragma unroll
            for (int j = 0; j < 9; j++) {
                int f = (lid & 1) + 2 * j;
                if (f < 17)
                    *(__nv_bfloat16*)(smem + SM_AHI + row * BSTR + 164 + 2 * f) =
                        __float2bfloat16(sM[row * 17 + f]);
            }
        }

        // gates h-part: kt 0..3 (all warps; fills the tensor pipe in this window)
        #pragma unroll
        for (int kt = 0; kt < 4; kt++) {
            u32 ah[4], al[4];
            LDSM4(ah, aHiAddr + kt * 32);
            LDSM4(al, aLoAddr + kt * 32);
            #pragma unroll
            for (int np = 0; np < 4; np++) {
                u32 bh[4], bl[4];
                LDSM4(bh, bHiAddr + np * (16 * BSTR) + kt * 32);
                LDSM4(bl, bLoAddr + np * (16 * BSTR) + kt * 32);
                MMA16816(cfr[2 * np],     ah, bh[0], bh[1]);
                MMA16816(cfr[2 * np],     al, bh[0], bh[1]);
                MMA16816(cfr[2 * np],     ah, bl[0], bl[1]);
                MMA16816(cfr[2 * np + 1], ah, bh[2], bh[3]);
                MMA16816(cfr[2 * np + 1], al, bh[2], bh[3]);
                MMA16816(cfr[2 * np + 1], ah, bl[2], bl[3]);
            }
        }

        // x_h epilogue: xc, loss, imputation, write A xc-cols (k 64..80)
        if (wn < 3) {
            int f0 = wn * 8 + (lid & 3) * 2;
            if (f0 < 17) {
                #pragma unroll
                for (int half = 0; half < 2; half++) {
                    int r = wm * 16 + (lid >> 2) + half * 8;
                    float acc0 = cx[2 * half] + sBreg[f0];
                    float xv0 = sX[r * 17 + f0];
                    float mv0 = sM[r * 17 + f0];
                    float xc0 = mv0 * xv0 + (1.0f - mv0) * acc0;
                    lnum += fabsf(xv0 - acc0) * mv0;
                    lden += mv0;
                    out_imp[(bb + r) * (T * F) + t * F + f0] = xc0;
                    if (f0 < 16) {
                        float acc1 = cx[2 * half + 1] + sBreg[f0 + 1];
                        float xv1 = sX[r * 17 + f0 + 1];
                        float mv1 = sM[r * 17 + f0 + 1];
                        float xc1 = mv1 * xv1 + (1.0f - mv1) * acc1;
                        lnum += fabsf(xv1 - acc1) * mv1;
                        lden += mv1;
                        out_imp[(bb + r) * (T * F) + t * F + f0 + 1] = xc1;
                        *(u32*)(smem + SM_AHI + r * BSTR + 128 + 2 * f0) = pk_hi(xc0, xc1);
                        *(u32*)(smem + SM_ALO + r * BSTR + 128 + 2 * f0) = pk_lo(xc0, xc1);
                    } else {  // f0 == 16 (don't clobber ones col at byte 162)
                        __nv_bfloat16 xhi = __float2bfloat16(xc0);
                        *(__nv_bfloat16*)(smem + SM_AHI + r * BSTR + 128 + 2 * f0) = xhi;
                        *(__nv_bfloat16*)(smem + SM_ALO + r * BSTR + 128 + 2 * f0) =
                            __float2bfloat16(xc0 - __bfloat162float(xhi));
                    }
                }
            }
        }
        #pragma unroll
        for (int ofs = 16; ofs > 0; ofs >>= 1) {
            lnum += __shfl_down_sync(0xFFFFFFFFu, lnum, ofs);
            lden += __shfl_down_sync(0xFFFFFFFFu, lden, ofs);
        }
        if (lid == 0) { sRed[wid] = lnum; sRed[NW + wid] = lden; }
        __syncthreads();   // A complete (xc+m), sRed ready
        if (tid == 0) {
            float n = 0.0f, d = 0.0f;
            #pragma unroll
            for (int i = 0; i < NW; i++) { n += sRed[i]; d += sRed[NW + i]; }
            g_num[t * NB + blockIdx.x] = n;
            g_den[t * NB + blockIdx.x] = d;
        }

        // ---- store prefetched t+1 inputs (overlaps phase B MMA) ----
        if (t + 1 < T) {
            #pragma unroll
            for (int j = 0; j < 2; j++) {
                float xv = pX[j];
                xv = (xv != xv) ? 0.0f : xv;
                sX[prR[j] * 17 + prF[j]] = xv;
                sM[prR[j] * 17 + prF[j]] = pM[j];
                sD[prR[j] * 17 + prF[j]] = pD[j];
            }
            if (pf3) {
                float xv = pX[2];
                xv = (xv != xv) ? 0.0f : xv;
                sX[prR[2] * 17 + prF[2]] = xv;
                sM[prR[2] * 17 + prF[2]] = pM[2];
                sD[prR[2] * 17 + prF[2]] = pD[2];
            }
        }

        // ==== phase B: gates kt 4..6 (Alo skipped at kt6 — structurally zero) ====
        #pragma unroll
        for (int kt = 4; kt < 7; kt++) {
            u32 ah[4], al[4];
            LDSM4(ah, aHiAddr + kt * 32);
            if (kt < 6) LDSM4(al, aLoAddr + kt * 32);
            #pragma unroll
            for (int np = 0; np < 4; np++) {
                u32 bh[4], bl[4];
                LDSM4(bh, bHiAddr + np * (16 * BSTR) + kt * 32);
                LDSM4(bl, bLoAddr + np * (16 * BSTR) + kt * 32);
                MMA16816(cfr[2 * np],     ah, bh[0], bh[1]);
                if (kt < 6) MMA16816(cfr[2 * np], al, bh[0], bh[1]);
                MMA16816(cfr[2 * np],     ah, bl[0], bl[1]);
                MMA16816(cfr[2 * np + 1], ah, bh[2], bh[3]);
                if (kt < 6) MMA16816(cfr[2 * np + 1], al, bh[2], bh[3]);
                MMA16816(cfr[2 * np + 1], ah, bl[2], bl[3]);
            }
        }

        // ---- LSTM epilogue ----
        #pragma unroll
        for (int tile = 0; tile < 8; tile++) {
            float e0 = __shfl_xor_sync(0xFFFFFFFFu, cfr[tile][0], 1);
            float e1 = __shfl_xor_sync(0xFFFFFFFFu, cfr[tile][1], 1);
            float e2 = __shfl_xor_sync(0xFFFFFFFFu, cfr[tile][2], 1);
            float e3 = __shfl_xor_sync(0xFFFFFFFFu, cfr[tile][3], 1);
            float gi, gf, gg, go;
            if (rpar == 0) { gi = cfr[tile][0]; gf = cfr[tile][1]; gg = e0; go = e1; }
            else           { gi = e2; gf = e3; gg = cfr[tile][2]; go = cfr[tile][3]; }
            float iv = sigm(gi), fv = sigm(gf);
            float gv = tanhax(gg), ov = sigm(go);
            float cc = fv * c_reg[tile] + iv * gv;
            c_reg[tile] = cc;
            h_reg[tile] = ov * tanhax(cc);
        }
    }

    // ---- y_h = h_final @ Wout^T + bout ----
    {
        float ph = 0.0f;
        #pragma unroll
        for (int tile = 0; tile < 8; tile++)
            ph += h_reg[tile] * sWout[wn * 16 + tile * 2 + hsel];
        sY[myrow * 8 + wn * 2 + hsel] = ph;
    }
    __syncthreads();
    if (tid < BT) {
        float acc = sBout[0];
        #pragma unroll
        for (int i = 0; i < 8; i++) acc += sY[tid * 8 + i];
        out_yh[bb + tid] = acc;
    }

    // ---- folded finalize ----
    if (tid == 0) {
        __threadfence();
        unsigned int prev = atomicAdd(&g_cnt, 1u);
        sFlag[0] = (prev == NB - 1) ? 1 : 0;
    }
    __syncthreads();
    if (sFlag[0]) {
        __threadfence();
        float v = 0.0f;
        if (tid < T) {
            float n = 0.0f, d = 0.0f;
            for (int b = 0; b < NB; b++) {
                n += g_num[tid * NB + b];
                d += g_den[tid * NB + b];
            }
            v = n / (d + 1e-5f);
        }
        if (tid < 64) sSv[tid] = v;
        __syncthreads();
        if (tid < 32) {
            float x = sSv[tid] + sSv[tid + 32];
            #pragma unroll
            for (int ofs = 16; ofs > 0; ofs >>= 1)
                x += __shfl_down_sync(0xFFFFFFFFu, x, ofs);
            if (tid == 0) {
                out_loss[0] = x;
                g_cnt = 0;
            }
        }
    }
}

extern "C" void kernel_launch(void* const* d_in, const int* in_sizes, int n_in,
                              void* d_out, int out_size) {
    const float* values = (const float*)d_in[0];
    const float* masks  = (const float*)d_in[1];
    const float* deltas = (const float*)d_in[2];
    const float* Wtd    = (const float*)d_in[3];
    const float* btd    = (const float*)d_in[4];
    const float* Wreg   = (const float*)d_in[5];
    const float* breg   = (const float*)d_in[6];
    const float* Wih    = (const float*)d_in[7];
    const float* Whh    = (const float*)d_in[8];
    const float* bih    = (const float*)d_in[9];
    const float* bhh    = (const float*)d_in[10];
    const float* Wout   = (const float*)d_in[11];
    const float* bout   = (const float*)d_in[12];

    float* out = (float*)d_out;
    float* out_loss = out;
    float* out_imp  = out + 1;
    float* out_yh   = out + 1 + BATCH * T * F;

    cudaFuncSetAttribute(grud_kernel,
                         cudaFuncAttributeMaxDynamicSharedMemorySize, SM_TOTAL);
    grud_kernel<<<NB, NTHREADS, SM_TOTAL>>>(
        values, masks, deltas, Wtd, btd, Wreg, breg,
        Wih, Whh, bih, bhh, Wout, bout, out_loss, out_imp, out_yh);
}

// round 9
// speedup vs baseline: 2.7636x; 1.0525x over previous
#include <cuda_runtime.h>
#include <cuda_bf16.h>

#define BATCH 8192
#define T 50
#define F 17
#define HID 64
#define BT 64
#define NB (BATCH/BT)   // 128 blocks
#define NTHREADS 512
#define NW 16
#define BSTR 240        // bytes per bf16-tile row
#define ABUF_SZ 30720   // one A buffer: hi(15360) + lo(15360)

// k layout of A / gates-B: [h 0..63][m 64..80][one 81][xc 82..98][pad 99..111]

typedef unsigned int u32;

__device__ float g_num[T * NB];
__device__ float g_den[T * NB];
__device__ unsigned int g_cnt;

// ---- smem byte offsets ----
#define SM_BHI   0          // 256*240 = 61440
#define SM_BLO   61440
#define SM_A0    122880     // 2 buffers x (hi+lo) = 61440
#define SM_WRGH  184320     // 24*144 = 3456
#define SM_WRGL  187776
#define SM_X     191232     // [2][64][17] f32 = 8704
#define SM_M     199936     // 8704
#define SM_D     208640     // [2][64][20] f32 = 10240
#define SM_WTD   218880     // [64][20] f32 = 5120
#define SM_WOUT  224000
#define SM_BTD   224256
#define SM_BREG  224512
#define SM_Y     224608     // 64*8*4 = 2048
#define SM_RED   226656
#define SM_SV    226784
#define SM_BOUT  227040
#define SM_FLAG  227044
#define SM_TOTAL 227072

__device__ __forceinline__ u32 smem_u32(const void* p) {
    u32 a;
    asm("{ .reg .u64 t; cvta.to.shared.u64 t, %1; cvt.u32.u64 %0, t; }" : "=r"(a) : "l"(p));
    return a;
}
__device__ __forceinline__ float tanhax(float x) {
    float r;
    asm("tanh.approx.f32 %0, %1;" : "=f"(r) : "f"(x));
    return r;
}
__device__ __forceinline__ float sigm(float x) {
    return fmaf(0.5f, tanhax(0.5f * x), 0.5f);
}
__device__ __forceinline__ u32 pk_hi(float a, float b) {
    return (u32)__bfloat16_as_ushort(__float2bfloat16(a)) |
           ((u32)__bfloat16_as_ushort(__float2bfloat16(b)) << 16);
}
__device__ __forceinline__ u32 pk_lo(float a, float b) {
    float ra = a - __bfloat162float(__float2bfloat16(a));
    float rb = b - __bfloat162float(__float2bfloat16(b));
    return pk_hi(ra, rb);
}

#define LDSM4(r, addr) \
    asm volatile("ldmatrix.sync.aligned.m8n8.x4.shared.b16 {%0,%1,%2,%3}, [%4];" \
        : "=r"((r)[0]), "=r"((r)[1]), "=r"((r)[2]), "=r"((r)[3]) : "r"(addr))
#define LDSM2(r, addr) \
    asm volatile("ldmatrix.sync.aligned.m8n8.x2.shared.b16 {%0,%1}, [%2];" \
        : "=r"((r)[0]), "=r"((r)[1]) : "r"(addr))

#define MMA16816(c, a, b0, b1) \
    asm volatile("mma.sync.aligned.m16n8k16.row.col.f32.bf16.bf16.f32 " \
        "{%0,%1,%2,%3}, {%4,%5,%6,%7}, {%8,%9}, {%0,%1,%2,%3};" \
        : "+f"((c)[0]), "+f"((c)[1]), "+f"((c)[2]), "+f"((c)[3]) \
        : "r"((a)[0]), "r"((a)[1]), "r"((a)[2]), "r"((a)[3]), "r"(b0), "r"(b1))

__global__ void __launch_bounds__(NTHREADS, 1)
grud_kernel(const float* __restrict__ values,
            const float* __restrict__ masks,
            const float* __restrict__ deltas,
            const float* __restrict__ Wtd, const float* __restrict__ btd,
            const float* __restrict__ Wreg, const float* __restrict__ breg,
            const float* __restrict__ Wih, const float* __restrict__ Whh,
            const float* __restrict__ bih, const float* __restrict__ bhh,
            const float* __restrict__ Wout, const float* __restrict__ bout,
            float* __restrict__ out_loss,
            float* __restrict__ out_imp,
            float* __restrict__ out_yh)
{
    extern __shared__ __align__(128) char smem[];
    const u32 sbase = smem_u32(smem);
    float* sX    = (float*)(smem + SM_X);     // [2][64][17]
    float* sM    = (float*)(smem + SM_M);
    float* sD    = (float*)(smem + SM_D);     // [2][64][20]
    float* sWtd  = (float*)(smem + SM_WTD);   // [64][20]
    float* sWout = (float*)(smem + SM_WOUT);
    float* sBtd  = (float*)(smem + SM_BTD);
    float* sBreg = (float*)(smem + SM_BREG);
    float* sY    = (float*)(smem + SM_Y);     // [64][8]
    float* sRed  = (float*)(smem + SM_RED);
    float* sSv   = (float*)(smem + SM_SV);
    float* sBout = (float*)(smem + SM_BOUT);
    int*   sFlag = (int*)(smem + SM_FLAG);

    const int tid = threadIdx.x;
    const int wid = tid >> 5;
    const int lid = tid & 31;
    const int wm = wid & 3;              // M tile (16 rows)
    const int wn = wid >> 2;             // N chunk
    const int hsel = (lid & 3) >> 1;
    const int rpar = lid & 1;
    const int myrow = wm * 16 + (lid >> 2) + rpar * 8;
    const int bb = blockIdx.x * BT;

    // ---- prezero both A buffers (hi+lo) and Wreg tiles ----
    for (int i = tid; i < (2 * ABUF_SZ) / 4; i += NTHREADS)
        ((u32*)(smem + SM_A0))[i] = 0u;
    for (int i = tid; i < (24 * 144) / 4; i += NTHREADS) {
        ((u32*)(smem + SM_WRGH))[i] = 0u;
        ((u32*)(smem + SM_WRGL))[i] = 0u;
    }
    // ---- build gates B hi/lo tiles: [n][k], n = hid*4 + gate ----
    for (int i = tid; i < 256 * 112; i += NTHREADS) {
        int n = i / 112, k = i % 112;
        int out = (n & 3) * 64 + (n >> 2);
        float w = 0.0f;
        if (k < 64)       w = Whh[out * 64 + k];
        else if (k < 81)  w = Wih[out * 34 + 17 + (k - 64)];  // m part
        else if (k == 81) w = bih[out] + bhh[out];            // bias (ones col)
        else if (k < 99)  w = Wih[out * 34 + (k - 82)];       // xc part
        __nv_bfloat16 whi = __float2bfloat16(w);
        float wlo = w - __bfloat162float(whi);
        *(__nv_bfloat16*)(smem + SM_BHI + n * BSTR + k * 2) = whi;
        *(__nv_bfloat16*)(smem + SM_BLO + n * BSTR + k * 2) = __float2bfloat16(wlo);
    }
    __syncthreads();
    // ---- Wreg^T hi/lo tile [f][k] ----
    for (int i = tid; i < F * HID; i += NTHREADS) {
        int f = i / HID, k = i % HID;
        float w = Wreg[f * HID + k];
        __nv_bfloat16 whi = __float2bfloat16(w);
        *(__nv_bfloat16*)(smem + SM_WRGH + f * 144 + k * 2) = whi;
        *(__nv_bfloat16*)(smem + SM_WRGL + f * 144 + k * 2) =
            __float2bfloat16(w - __bfloat162float(whi));
    }
    for (int i = tid; i < HID * F; i += NTHREADS) {
        int h = i / F, k = i % F;
        sWtd[h * 20 + k] = Wtd[h * F + k];
    }
    if (tid < HID) sBtd[tid] = btd[tid];
    if (tid < F)   sBreg[tid] = breg[tid];
    if (tid < HID) sWout[tid] = Wout[tid];
    if (tid == 0)  sBout[0] = bout[0];
    // ones column (k=81 -> byte 162), both buffers
    if (tid < BT) {
        *(__nv_bfloat16*)(smem + SM_A0 + tid * BSTR + 162) = __float2bfloat16(1.0f);
        *(__nv_bfloat16*)(smem + SM_A0 + ABUF_SZ + tid * BSTR + 162) = __float2bfloat16(1.0f);
    }
    // t=0 inputs -> buffer 0 (+ m bf16 cols into A buf0)
    for (int o = tid; o < BT * F; o += NTHREADS) {
        int r = o / F, f = o % F;
        int base = (bb + r) * (T * F) + f;
        float xv = values[base];
        xv = (xv != xv) ? 0.0f : xv;
        float mv = masks[base];
        sX[r * 17 + f] = xv;
        sM[r * 17 + f] = mv;
        sD[r * 20 + f] = deltas[base];
        *(__nv_bfloat16*)(smem + SM_A0 + r * BSTR + 128 + 2 * f) = __float2bfloat16(mv);
    }
    __syncthreads();

    // ---- ldmatrix lane address bases (buffer 0) ----
    const u32 aHiBase = sbase + SM_A0 +
        (u32)((wm * 16 + (lid & 7) + ((lid >> 3) & 1) * 8) * BSTR + ((lid >> 4) & 1) * 16);
    const u32 bHiAddr = sbase + SM_BHI +
        (u32)((wn * 64 + ((lid >> 4) & 1) * 8 + (lid & 7)) * BSTR + ((lid >> 3) & 1) * 16);
    const u32 bLoAddr = bHiAddr + (SM_BLO - SM_BHI);
    const u32 wrgHAddr = sbase + SM_WRGH +
        (u32)((wn * 8 + (lid & 7)) * 144 + ((lid >> 3) & 1) * 16);
    const u32 wrgLAddr = wrgHAddr + (SM_WRGL - SM_WRGH);

    // ---- hoisted prefetch indices ----
    int prR[3], prF[3], prB[3];
    #pragma unroll
    for (int j = 0; j < 3; j++) {
        int o = tid + j * NTHREADS;
        int r = o / F, f = o - r * F;
        prR[j] = r; prF[j] = f;
        prB[j] = (bb + r) * (T * F) + f;
    }
    const bool pf3 = (tid < BT * F - 2 * NTHREADS);

    float h_reg[8], c_reg[8];
    #pragma unroll
    for (int i = 0; i < 8; i++) { h_reg[i] = 0.0f; c_reg[i] = 0.0f; }

    for (int t = 0; t < T; t++) {
        const int cur = t & 1;
        const int nxt = cur ^ 1;
        const u32 curA = (u32)cur * ABUF_SZ;
        const u32 nxtA = (u32)nxt * ABUF_SZ;
        const u32 aHiAddr = aHiBase + curA;
        const u32 aLoAddr = aHiAddr + 15360;

        // ---- prefetch t+1 into registers ----
        float pX[3], pM[3], pD[3];
        if (t + 1 < T) {
            #pragma unroll
            for (int j = 0; j < 2; j++) {
                int base = prB[j] + (t + 1) * F;
                pX[j] = values[base]; pM[j] = masks[base]; pD[j] = deltas[base];
            }
            if (pf3) {
                int base = prB[2] + (t + 1) * F;
                pX[2] = values[base]; pM[2] = masks[base]; pD[2] = deltas[base];
            }
        }

        // ---- phase 2: gamma, hd = h*gamma -> A[cur] h-cols (k 0..63) ----
        // (overlaps other warps' phaseB of step t-1 — no sync needed: different A buffer)
        {
            const float* dvp = &sD[cur * 1280 + myrow * 20];
            float4 d0 = *(const float4*)&dvp[0];
            float4 d1 = *(const float4*)&dvp[4];
            float4 d2 = *(const float4*)&dvp[8];
            float4 d3 = *(const float4*)&dvp[12];
            float  d16 = dvp[16];
            #pragma unroll
            for (int tile = 0; tile < 8; tile++) {
                int hid = wn * 16 + tile * 2 + hsel;
                const float* wt = &sWtd[hid * 20];
                float4 w0 = *(const float4*)&wt[0];
                float4 w1 = *(const float4*)&wt[4];
                float4 w2 = *(const float4*)&wt[8];
                float4 w3 = *(const float4*)&wt[12];
                float acc = sBtd[hid] + d16 * wt[16];
                acc += d0.x*w0.x + d0.y*w0.y + d0.z*w0.z + d0.w*w0.w;
                acc += d1.x*w1.x + d1.y*w1.y + d1.z*w1.z + d1.w*w1.w;
                acc += d2.x*w2.x + d2.y*w2.y + d2.z*w2.z + d2.w*w2.w;
                acc += d3.x*w3.x + d3.y*w3.y + d3.z*w3.z + d3.w*w3.w;
                float gamma = __expf(-fmaxf(acc, 0.0f));
                float hd = h_reg[tile] * gamma;
                float hdp = __shfl_xor_sync(0xFFFFFFFFu, hd, 2);
                if (hsel == 0) {
                    int word = wn * 8 + tile;
                    *(u32*)(smem + SM_A0 + curA + myrow * BSTR + word * 4) = pk_hi(hd, hdp);
                    *(u32*)(smem + SM_A0 + curA + 15360 + myrow * BSTR + word * 4) = pk_lo(hd, hdp);
                }
            }
        }
        __syncthreads();   // #1: A[cur] h-cols ready; prev phaseB complete everywhere

        // ==== phase A ====
        float cfr[8][4];
        #pragma unroll
        for (int i = 0; i < 8; i++)
            #pragma unroll
            for (int j = 0; j < 4; j++) cfr[i][j] = 0.0f;

        float lnum = 0.0f, lden = 0.0f;
        float cx[4] = {0.0f, 0.0f, 0.0f, 0.0f};

        if (wn < 3) {
            // x_h MMA over h k-tiles 0..3
            #pragma unroll
            for (int kt = 0; kt < 4; kt++) {
                u32 ah[4], al[4], bh[2], bl[2];
                LDSM4(ah, aHiAddr + kt * 32);
                LDSM4(al, aLoAddr + kt * 32);
                LDSM2(bh, wrgHAddr + kt * 32);
                LDSM2(bl, wrgLAddr + kt * 32);
                MMA16816(cx, ah, bh[0], bh[1]);
                MMA16816(cx, al, bh[0], bh[1]);
                MMA16816(cx, ah, bl[0], bl[1]);
            }
        }

        // gates kt0..3 (full 3 passes) — fills tensor pipe in x_h window
        #pragma unroll
        for (int kt = 0; kt < 4; kt++) {
            u32 ah[4], al[4];
            LDSM4(ah, aHiAddr + kt * 32);
            LDSM4(al, aLoAddr + kt * 32);
            #pragma unroll
            for (int np = 0; np < 4; np++) {
                u32 bh[4], bl[4];
                LDSM4(bh, bHiAddr + np * (16 * BSTR) + kt * 32);
                LDSM4(bl, bLoAddr + np * (16 * BSTR) + kt * 32);
                MMA16816(cfr[2 * np],     ah, bh[0], bh[1]);
                MMA16816(cfr[2 * np],     al, bh[0], bh[1]);
                MMA16816(cfr[2 * np],     ah, bl[0], bl[1]);
                MMA16816(cfr[2 * np + 1], ah, bh[2], bh[3]);
                MMA16816(cfr[2 * np + 1], al, bh[2], bh[3]);
                MMA16816(cfr[2 * np + 1], ah, bl[2], bl[3]);
            }
        }
        // gates kt4 (m cols: A-lo structurally zero -> skip Alo pass)
        {
            u32 ah[4];
            LDSM4(ah, aHiAddr + 4 * 32);
            #pragma unroll
            for (int np = 0; np < 4; np++) {
                u32 bh[4], bl[4];
                LDSM4(bh, bHiAddr + np * (16 * BSTR) + 4 * 32);
                LDSM4(bl, bLoAddr + np * (16 * BSTR) + 4 * 32);
                MMA16816(cfr[2 * np],     ah, bh[0], bh[1]);
                MMA16816(cfr[2 * np],     ah, bl[0], bl[1]);
                MMA16816(cfr[2 * np + 1], ah, bh[2], bh[3]);
                MMA16816(cfr[2 * np + 1], ah, bl[2], bl[3]);
            }
        }

        // x_h epilogue: xc, loss, imputation, write A[cur] xc-cols (k 82..98)
        if (wn < 3) {
            int f0 = wn * 8 + (lid & 3) * 2;
            if (f0 < 17) {
                #pragma unroll
                for (int half = 0; half < 2; half++) {
                    int r = wm * 16 + (lid >> 2) + half * 8;
                    float acc0 = cx[2 * half] + sBreg[f0];
                    float xv0 = sX[cur * 1088 + r * 17 + f0];
                    float mv0 = sM[cur * 1088 + r * 17 + f0];
                    float xc0 = mv0 * xv0 + (1.0f - mv0) * acc0;
                    lnum += fabsf(xv0 - acc0) * mv0;
                    lden += mv0;
                    out_imp[(bb + r) * (T * F) + t * F + f0] = xc0;
                    float xc1 = 0.0f;
                    if (f0 < 16) {
                        float acc1 = cx[2 * half + 1] + sBreg[f0 + 1];
                        float xv1 = sX[cur * 1088 + r * 17 + f0 + 1];
                        float mv1 = sM[cur * 1088 + r * 17 + f0 + 1];
                        xc1 = mv1 * xv1 + (1.0f - mv1) * acc1;
                        lnum += fabsf(xv1 - acc1) * mv1;
                        lden += mv1;
                        out_imp[(bb + r) * (T * F) + t * F + f0 + 1] = xc1;
                    }
                    *(u32*)(smem + SM_A0 + curA + r * BSTR + 164 + 2 * f0) = pk_hi(xc0, xc1);
                    *(u32*)(smem + SM_A0 + curA + 15360 + r * BSTR + 164 + 2 * f0) = pk_lo(xc0, xc1);
                }
            }
        }
        #pragma unroll
        for (int ofs = 16; ofs > 0; ofs >>= 1) {
            lnum += __shfl_down_sync(0xFFFFFFFFu, lnum, ofs);
            lden += __shfl_down_sync(0xFFFFFFFFu, lden, ofs);
        }
        if (lid == 0) { sRed[wid] = lnum; sRed[NW + wid] = lden; }

        // ---- prefetch stores -> buffers[nxt] + A[nxt] m-cols (safe after sync#1) ----
        if (t + 1 < T) {
            #pragma unroll
            for (int j = 0; j < 3; j++) {
                if (j == 2 && !pf3) break;
                float xv = pX[j];
                xv = (xv != xv) ? 0.0f : xv;
                int r = prR[j], f = prF[j];
                sX[nxt * 1088 + r * 17 + f] = xv;
                sM[nxt * 1088 + r * 17 + f] = pM[j];
                sD[nxt * 1280 + r * 20 + f] = pD[j];
                *(__nv_bfloat16*)(smem + SM_A0 + nxtA + r * BSTR + 128 + 2 * f) =
                    __float2bfloat16(pM[j]);
            }
        }
        __syncthreads();   // #2: A[cur] complete (xc), nxt inputs visible, sRed ready
        if (tid == 0) {
            float n = 0.0f, d = 0.0f;
            #pragma unroll
            for (int i = 0; i < NW; i++) { n += sRed[i]; d += sRed[NW + i]; }
            g_num[t * NB + blockIdx.x] = n;
            g_den[t * NB + blockIdx.x] = d;
        }

        // ==== phase B: gates kt5..6 (xc-dependent) ====
        #pragma unroll
        for (int kt = 5; kt < 7; kt++) {
            u32 ah[4], al[4];
            LDSM4(ah, aHiAddr + kt * 32);
            LDSM4(al, aLoAddr + kt * 32);
            #pragma unroll
            for (int np = 0; np < 4; np++) {
                u32 bh[4], bl[4];
                LDSM4(bh, bHiAddr + np * (16 * BSTR) + kt * 32);
                LDSM4(bl, bLoAddr + np * (16 * BSTR) + kt * 32);
                MMA16816(cfr[2 * np],     ah, bh[0], bh[1]);
                MMA16816(cfr[2 * np],     al, bh[0], bh[1]);
                MMA16816(cfr[2 * np],     ah, bl[0], bl[1]);
                MMA16816(cfr[2 * np + 1], ah, bh[2], bh[3]);
                MMA16816(cfr[2 * np + 1], al, bh[2], bh[3]);
                MMA16816(cfr[2 * np + 1], ah, bl[2], bl[3]);
            }
        }

        // ---- LSTM epilogue ----
        #pragma unroll
        for (int tile = 0; tile < 8; tile++) {
            float e0 = __shfl_xor_sync(0xFFFFFFFFu, cfr[tile][0], 1);
            float e1 = __shfl_xor_sync(0xFFFFFFFFu, cfr[tile][1], 1);
            float e2 = __shfl_xor_sync(0xFFFFFFFFu, cfr[tile][2], 1);
            float e3 = __shfl_xor_sync(0xFFFFFFFFu, cfr[tile][3], 1);
            float gi, gf, gg, go;
            if (rpar == 0) { gi = cfr[tile][0]; gf = cfr[tile][1]; gg = e0; go = e1; }
            else           { gi = e2; gf = e3; gg = cfr[tile][2]; go = cfr[tile][3]; }
            float iv = sigm(gi), fv = sigm(gf);
            float gv = tanhax(gg), ov = sigm(go);
            float cc = fv * c_reg[tile] + iv * gv;
            c_reg[tile] = cc;
            h_reg[tile] = ov * tanhax(cc);
        }
    }

    // ---- y_h = h_final @ Wout^T + bout ----
    {
        float ph = 0.0f;
        #pragma unroll
        for (int tile = 0; tile < 8; tile++)
            ph += h_reg[tile] * sWout[wn * 16 + tile * 2 + hsel];
        sY[myrow * 8 + wn * 2 + hsel] = ph;
    }
    __syncthreads();
    if (tid < BT) {
        float acc = sBout[0];
        #pragma unroll
        for (int i = 0; i < 8; i++) acc += sY[tid * 8 + i];
        out_yh[bb + tid] = acc;
    }

    // ---- folded finalize ----
    if (tid == 0) {
        __threadfence();
        unsigned int prev = atomicAdd(&g_cnt, 1u);
        sFlag[0] = (prev == NB - 1) ? 1 : 0;
    }
    __syncthreads();
    if (sFlag[0]) {
        __threadfence();
        float v = 0.0f;
        if (tid < T) {
            float n = 0.0f, d = 0.0f;
            for (int b = 0; b < NB; b++) {
                n += g_num[tid * NB + b];
                d += g_den[tid * NB + b];
            }
            v = n / (d + 1e-5f);
        }
        if (tid < 64) sSv[tid] = v;
        __syncthreads();
        if (tid < 32) {
            float x = sSv[tid] + sSv[tid + 32];
            #pragma unroll
            for (int ofs = 16; ofs > 0; ofs >>= 1)
                x += __shfl_down_sync(0xFFFFFFFFu, x, ofs);
            if (tid == 0) {
                out_loss[0] = x;
                g_cnt = 0;
            }
        }
    }
}

extern "C" void kernel_launch(void* const* d_in, const int* in_sizes, int n_in,
                              void* d_out, int out_size) {
    const float* values = (const float*)d_in[0];
    const float* masks  = (const float*)d_in[1];
    const float* deltas = (const float*)d_in[2];
    const float* Wtd    = (const float*)d_in[3];
    const float* btd    = (const float*)d_in[4];
    const float* Wreg   = (const float*)d_in[5];
    const float* breg   = (const float*)d_in[6];
    const float* Wih    = (const float*)d_in[7];
    const float* Whh    = (const float*)d_in[8];
    const float* bih    = (const float*)d_in[9];
    const float* bhh    = (const float*)d_in[10];
    const float* Wout   = (const float*)d_in[11];
    const float* bout   = (const float*)d_in[12];

    float* out = (float*)d_out;
    float* out_loss = out;
    float* out_imp  = out + 1;
    float* out_yh   = out + 1 + BATCH * T * F;

    cudaFuncSetAttribute(grud_kernel,
                         cudaFuncAttributeMaxDynamicSharedMemorySize, SM_TOTAL);
    grud_kernel<<<NB, NTHREADS, SM_TOTAL>>>(
        values, masks, deltas, Wtd, btd, Wreg, breg,
        Wih, Whh, bih, bhh, Wout, bout, out_loss, out_imp, out_yh);
}